// round 4
// baseline (speedup 1.0000x reference)
#include <cuda_runtime.h>
#include <cuda_bf16.h>

#define N_NODES 100000
#define IN_FEAT 128
#define NOUT 256           // fused outputs per node: [A(128) | B(128)]

// Scratch: per-node precomputed A|B rows (102.4 MB) + fused/transposed weights.
__device__ float g_node[(size_t)N_NODES * NOUT];
__device__ float g_Wt[IN_FEAT * NOUT];   // layout [k][j'], j'<128 -> A-weights, j'>=128 -> B-weights

// ---------------------------------------------------------------------------
// Kernel 1: fuse + transpose W1 (128 x 256, row-major) into Wt[k][j']:
//   j' <  128: Wt[k][j'] = W1[j', k]           (A-half: W1 inputs 0..127 = src feats)
//   j' >= 128: Wt[k][j'] = W1[j'-128, 128+k]   (B-half: W1 inputs 128..255 = dst feats)
// ---------------------------------------------------------------------------
__global__ void fuse_weights_kernel(const float* __restrict__ W1) {
    int idx = blockIdx.x * blockDim.x + threadIdx.x;
    if (idx >= IN_FEAT * NOUT) return;
    int k = idx / NOUT;
    int j = idx % NOUT;
    float v = (j < IN_FEAT) ? W1[j * NOUT + k]
                            : W1[(j - IN_FEAT) * NOUT + IN_FEAT + k];
    g_Wt[idx] = v;
}

// ---------------------------------------------------------------------------
// Kernel 2: node GEMM  g_node[n, j'] = sum_k feat[n,k] * Wt[k][j']
// M = 100000, N = 256, K = 128. Classic 128x128x8 SMEM-tiled SGEMM, TM=TN=8.
// ---------------------------------------------------------------------------
#define BM 128
#define BN 128
#define BK 8
#define TM 8
#define TN 8

__global__ __launch_bounds__(256) void node_gemm_kernel(const float* __restrict__ feat) {
    __shared__ __align__(16) float As[BK][BM];   // feature tile, transposed
    __shared__ __align__(16) float Bs[BK][BN];   // weight tile

    const int tid = threadIdx.x;
    const int row0 = blockIdx.y * BM;        // node tile start
    const int col0 = blockIdx.x * BN;        // output tile start (0 or 128)

    const int tcol = tid % (BN / TN);        // 0..15
    const int trow = tid / (BN / TN);        // 0..15

    // A tile load: 128 rows x 8 k-cols, one float4 per thread along K
    const int aRow = tid >> 1;               // 0..127
    const int aCol = (tid & 1) * 4;          // 0 or 4
    // B tile load: 8 k-rows x 128 cols, one float4 per thread along N
    const int bRow = tid >> 5;               // 0..7
    const int bCol = (tid & 31) * 4;         // 0..124

    float acc[TM][TN];
    #pragma unroll
    for (int i = 0; i < TM; ++i)
        #pragma unroll
        for (int j = 0; j < TN; ++j) acc[i][j] = 0.f;

    for (int kt = 0; kt < IN_FEAT; kt += BK) {
        // load feature tile (guard rows past N_NODES)
        const int gr = row0 + aRow;
        float4 av = make_float4(0.f, 0.f, 0.f, 0.f);
        if (gr < N_NODES)
            av = *(const float4*)(feat + (size_t)gr * IN_FEAT + kt + aCol);
        As[aCol + 0][aRow] = av.x;
        As[aCol + 1][aRow] = av.y;
        As[aCol + 2][aRow] = av.z;
        As[aCol + 3][aRow] = av.w;

        // load weight tile (coalesced from pre-transposed Wt)
        *(float4*)&Bs[bRow][bCol] =
            *(const float4*)(g_Wt + (kt + bRow) * NOUT + col0 + bCol);

        __syncthreads();

        #pragma unroll
        for (int k = 0; k < BK; ++k) {
            float regM[TM], regN[TN];
            *(float4*)&regM[0] = *(const float4*)&As[k][trow * TM + 0];
            *(float4*)&regM[4] = *(const float4*)&As[k][trow * TM + 4];
            *(float4*)&regN[0] = *(const float4*)&Bs[k][tcol * TN + 0];
            *(float4*)&regN[4] = *(const float4*)&Bs[k][tcol * TN + 4];
            #pragma unroll
            for (int i = 0; i < TM; ++i)
                #pragma unroll
                for (int j = 0; j < TN; ++j)
                    acc[i][j] = fmaf(regM[i], regN[j], acc[i][j]);
        }
        __syncthreads();
    }

    // store 8x8 tile (two float4 per row)
    #pragma unroll
    for (int i = 0; i < TM; ++i) {
        const int gr = row0 + trow * TM + i;
        if (gr >= N_NODES) continue;
        float* dst = g_node + (size_t)gr * NOUT + col0 + tcol * TN;
        *(float4*)(dst + 0) = make_float4(acc[i][0], acc[i][1], acc[i][2], acc[i][3]);
        *(float4*)(dst + 4) = make_float4(acc[i][4], acc[i][5], acc[i][6], acc[i][7]);
    }
}

// ---------------------------------------------------------------------------
// Kernel 3: per-edge score. One warp per edge:
//   hid = relu(A[src] + B[dst] + b1)  (128 values, 4/lane via float4)
//   score = dot(hid, W2) + b2         (warp shuffle reduction)
// NOTE: src/dst are int32 (JAX x64 disabled -> randint int64 request silently
// yields int32). Indices clamped defensively so any residual assumption error
// shows up as rel_err, not a crash.
// ---------------------------------------------------------------------------
__global__ __launch_bounds__(256) void edge_score_kernel(
    const int* __restrict__ src,
    const int* __restrict__ dst,
    const float* __restrict__ b1,
    const float* __restrict__ W2,
    const float* __restrict__ b2,
    float* __restrict__ out,
    int E)
{
    const int warp = (blockIdx.x * blockDim.x + threadIdx.x) >> 5;
    const int lane = threadIdx.x & 31;
    if (warp >= E) return;

    int s = src[warp];
    int d = dst[warp];
    s = min(max(s, 0), N_NODES - 1);
    d = min(max(d, 0), N_NODES - 1);

    // A row = first 128 floats of g_node[s], B row = last 128 floats of g_node[d]
    const float4 a = ((const float4*)(g_node + (size_t)s * NOUT))[lane];
    const float4 b = ((const float4*)(g_node + (size_t)d * NOUT + IN_FEAT))[lane];
    const float4 bias = ((const float4*)b1)[lane];
    const float4 w = ((const float4*)W2)[lane];

    const float h0 = fmaxf(a.x + b.x + bias.x, 0.f);
    const float h1 = fmaxf(a.y + b.y + bias.y, 0.f);
    const float h2 = fmaxf(a.z + b.z + bias.z, 0.f);
    const float h3 = fmaxf(a.w + b.w + bias.w, 0.f);

    float p = fmaf(h0, w.x, fmaf(h1, w.y, fmaf(h2, w.z, h3 * w.w)));

    #pragma unroll
    for (int o = 16; o; o >>= 1)
        p += __shfl_xor_sync(0xffffffffu, p, o);

    if (lane == 0) out[warp] = p + b2[0];
}

// ---------------------------------------------------------------------------
// Launch
// Inputs (metadata order): 0 feature[100000,128] f32, 1 src[800000] i32,
// 2 dst[800000] i32, 3 W1[128,256] f32, 4 b1[128] f32, 5 W2[1,128] f32, 6 b2[1] f32
// Output: score[800000,1] f32
// ---------------------------------------------------------------------------
extern "C" void kernel_launch(void* const* d_in, const int* in_sizes, int n_in,
                              void* d_out, int out_size) {
    const float* feat = (const float*)d_in[0];
    const int*   src  = (const int*)d_in[1];
    const int*   dst  = (const int*)d_in[2];
    const float* W1   = (const float*)d_in[3];
    const float* b1   = (const float*)d_in[4];
    const float* W2   = (const float*)d_in[5];
    const float* b2   = (const float*)d_in[6];
    float*       out  = (float*)d_out;

    const int E = in_sizes[1];

    // 1) fuse/transpose weights (32768 elems)
    fuse_weights_kernel<<<(IN_FEAT * NOUT + 255) / 256, 256>>>(W1);

    // 2) per-node GEMM: grid (256/128 = 2, ceil(100000/128) = 782)
    dim3 ggrid(NOUT / BN, (N_NODES + BM - 1) / BM);
    node_gemm_kernel<<<ggrid, 256>>>(feat);

    // 3) per-edge score: one warp per edge, 8 warps/block
    const int nblocks = (E + 7) / 8;
    edge_score_kernel<<<nblocks, 256>>>(src, dst, b1, W2, b2, out, E);
}

// round 5
// speedup vs baseline: 1.0208x; 1.0208x over previous
#include <cuda_runtime.h>
#include <cuda_bf16.h>

#define N_NODES 100000
#define IN_FEAT 128
#define NOUT 256           // fused outputs per node: [A(128) | B(128)]

// Scratch: per-node precomputed A|B rows (102.4 MB) + fused/transposed weights.
__device__ float g_node[(size_t)N_NODES * NOUT];
__device__ float g_Wt[IN_FEAT * NOUT];   // [k][j']: j'<128 -> A-weights, j'>=128 -> B-weights

// ---------------------------------------------------------------------------
// Kernel 1: fuse + transpose W1 (128 x 256 row-major) into Wt[k][j'].
// ---------------------------------------------------------------------------
__global__ void fuse_weights_kernel(const float* __restrict__ W1) {
    int idx = blockIdx.x * blockDim.x + threadIdx.x;
    if (idx >= IN_FEAT * NOUT) return;
    int k = idx / NOUT;
    int j = idx % NOUT;
    float v = (j < IN_FEAT) ? W1[j * NOUT + k]
                            : W1[(j - IN_FEAT) * NOUT + IN_FEAT + k];
    g_Wt[idx] = v;
}

// ---------------------------------------------------------------------------
// Kernel 2: node GEMM  g_node[n, j'] = sum_k feat[n,k] * Wt[k][j']
// M = 100000, N = 256, K = 128. 128x128x8 SMEM-tiled, TM=TN=8.
// Inner product uses packed fma.rn.f32x2 (SASS FFMA2): 2 exact fp32 FMAs per
// instruction, accumulators packed along N.
// ---------------------------------------------------------------------------
#define BM 128
#define BN 128
#define BK 8
#define TM 8
#define TN 8

__device__ __forceinline__ unsigned long long pack_dup(float m) {
    unsigned long long r;
    unsigned int mu = __float_as_uint(m);
    asm("mov.b64 %0, {%1, %1};" : "=l"(r) : "r"(mu));
    return r;
}

__global__ __launch_bounds__(256, 2) void node_gemm_kernel(const float* __restrict__ feat) {
    __shared__ __align__(16) float As[BK][BM];   // feature tile, transposed
    __shared__ __align__(16) float Bs[BK][BN];   // weight tile

    const int tid = threadIdx.x;
    const int row0 = blockIdx.y * BM;        // node tile start
    const int col0 = blockIdx.x * BN;        // output tile start (0 or 128)

    const int tcol = tid % (BN / TN);        // 0..15
    const int trow = tid / (BN / TN);        // 0..15

    const int aRow = tid >> 1;               // 0..127
    const int aCol = (tid & 1) * 4;          // 0 or 4
    const int bRow = tid >> 5;               // 0..7
    const int bCol = (tid & 31) * 4;         // 0..124

    // Packed accumulators: acc2[i][j] = (acc[i][2j], acc[i][2j+1])
    unsigned long long acc2[TM][TN / 2];
    #pragma unroll
    for (int i = 0; i < TM; ++i)
        #pragma unroll
        for (int j = 0; j < TN / 2; ++j) acc2[i][j] = 0ull;

    for (int kt = 0; kt < IN_FEAT; kt += BK) {
        const int gr = row0 + aRow;
        float4 av = make_float4(0.f, 0.f, 0.f, 0.f);
        if (gr < N_NODES)
            av = *(const float4*)(feat + (size_t)gr * IN_FEAT + kt + aCol);
        As[aCol + 0][aRow] = av.x;
        As[aCol + 1][aRow] = av.y;
        As[aCol + 2][aRow] = av.z;
        As[aCol + 3][aRow] = av.w;

        *(float4*)&Bs[bRow][bCol] =
            *(const float4*)(g_Wt + (kt + bRow) * NOUT + col0 + bCol);

        __syncthreads();

        #pragma unroll
        for (int k = 0; k < BK; ++k) {
            float regM[TM];
            *(float4*)&regM[0] = *(const float4*)&As[k][trow * TM + 0];
            *(float4*)&regM[4] = *(const float4*)&As[k][trow * TM + 4];

            // N operands: 8 consecutive floats -> 4 packed f32x2 (free reinterpret)
            unsigned long long regN2[TN / 2];
            float4 n0 = *(const float4*)&Bs[k][tcol * TN + 0];
            float4 n1 = *(const float4*)&Bs[k][tcol * TN + 4];
            regN2[0] = ((const unsigned long long*)&n0)[0];
            regN2[1] = ((const unsigned long long*)&n0)[1];
            regN2[2] = ((const unsigned long long*)&n1)[0];
            regN2[3] = ((const unsigned long long*)&n1)[1];

            #pragma unroll
            for (int i = 0; i < TM; ++i) {
                const unsigned long long m2 = pack_dup(regM[i]);
                #pragma unroll
                for (int j = 0; j < TN / 2; ++j)
                    asm("fma.rn.f32x2 %0, %1, %2, %0;"
                        : "+l"(acc2[i][j]) : "l"(m2), "l"(regN2[j]));
            }
        }
        __syncthreads();
    }

    // store 8x8 tile: acc2[i][0..3] are 8 consecutive floats
    #pragma unroll
    for (int i = 0; i < TM; ++i) {
        const int gr = row0 + trow * TM + i;
        if (gr >= N_NODES) continue;
        float* dst = g_node + (size_t)gr * NOUT + col0 + tcol * TN;
        *(float4*)(dst + 0) = *(const float4*)&acc2[i][0];
        *(float4*)(dst + 4) = *(const float4*)&acc2[i][2];
    }
}

// ---------------------------------------------------------------------------
// Kernel 3: per-edge score. One warp per edge:
//   hid = relu(A[src] + B[dst] + b1); score = dot(hid, W2) + b2
// src/dst are int32 (JAX x64 disabled). Indices clamped defensively.
// ---------------------------------------------------------------------------
__global__ __launch_bounds__(256) void edge_score_kernel(
    const int* __restrict__ src,
    const int* __restrict__ dst,
    const float* __restrict__ b1,
    const float* __restrict__ W2,
    const float* __restrict__ b2,
    float* __restrict__ out,
    int E)
{
    const int warp = (blockIdx.x * blockDim.x + threadIdx.x) >> 5;
    const int lane = threadIdx.x & 31;
    if (warp >= E) return;

    int s = src[warp];
    int d = dst[warp];
    s = min(max(s, 0), N_NODES - 1);
    d = min(max(d, 0), N_NODES - 1);

    const float4 a = ((const float4*)(g_node + (size_t)s * NOUT))[lane];
    const float4 b = ((const float4*)(g_node + (size_t)d * NOUT + IN_FEAT))[lane];
    const float4 bias = ((const float4*)b1)[lane];
    const float4 w = ((const float4*)W2)[lane];

    const float h0 = fmaxf(a.x + b.x + bias.x, 0.f);
    const float h1 = fmaxf(a.y + b.y + bias.y, 0.f);
    const float h2 = fmaxf(a.z + b.z + bias.z, 0.f);
    const float h3 = fmaxf(a.w + b.w + bias.w, 0.f);

    float p = fmaf(h0, w.x, fmaf(h1, w.y, fmaf(h2, w.z, h3 * w.w)));

    #pragma unroll
    for (int o = 16; o; o >>= 1)
        p += __shfl_xor_sync(0xffffffffu, p, o);

    if (lane == 0) out[warp] = p + b2[0];
}

// ---------------------------------------------------------------------------
// Launch.  Inputs: 0 feature[100000,128] f32, 1 src[800000] i32,
// 2 dst[800000] i32, 3 W1[128,256] f32, 4 b1[128] f32, 5 W2[1,128] f32,
// 6 b2[1] f32.  Output: score[800000,1] f32.
// ---------------------------------------------------------------------------
extern "C" void kernel_launch(void* const* d_in, const int* in_sizes, int n_in,
                              void* d_out, int out_size) {
    const float* feat = (const float*)d_in[0];
    const int*   src  = (const int*)d_in[1];
    const int*   dst  = (const int*)d_in[2];
    const float* W1   = (const float*)d_in[3];
    const float* b1   = (const float*)d_in[4];
    const float* W2   = (const float*)d_in[5];
    const float* b2   = (const float*)d_in[6];
    float*       out  = (float*)d_out;

    const int E = in_sizes[1];

    fuse_weights_kernel<<<(IN_FEAT * NOUT + 255) / 256, 256>>>(W1);

    dim3 ggrid(NOUT / BN, (N_NODES + BM - 1) / BM);
    node_gemm_kernel<<<ggrid, 256>>>(feat);

    const int nblocks = (E + 7) / 8;
    edge_score_kernel<<<nblocks, 256>>>(src, dst, b1, W2, b2, out, E);
}

// round 7
// speedup vs baseline: 1.4658x; 1.4359x over previous
#include <cuda_runtime.h>
#include <cuda_bf16.h>
#include <cstdint>

#define N_NODES 100000
#define IN_FEAT 128
#define NOUT 256           // fused outputs per node: [A(128) | B(128)]

// Scratch: per-node A|B rows (fp32, 102.4 MB) + split bf16 weights [j][k] K-major.
__device__ float g_node[(size_t)N_NODES * NOUT];
__device__ __align__(16) __nv_bfloat16 g_Whi[NOUT * IN_FEAT];
__device__ __align__(16) __nv_bfloat16 g_Wlo[NOUT * IN_FEAT];

__device__ __forceinline__ uint32_t s2u(const void* p) {
    uint32_t a;
    asm("{ .reg .u64 t; cvta.to.shared.u64 t, %1; cvt.u32.u64 %0, t; }" : "=r"(a) : "l"(p));
    return a;
}
__device__ __forceinline__ uint32_t pk(__nv_bfloat16 a, __nv_bfloat16 b) {
    __nv_bfloat162 t(a, b);
    return *reinterpret_cast<uint32_t*>(&t);
}

// ---------------------------------------------------------------------------
// Kernel 1: fuse + transpose + bf16-split W1 (128x256 row-major) -> Whi/Wlo[j][k]
//   j<128: W1[j,k] (src half);  j>=128: W1[j-128, 128+k] (dst half)
// ---------------------------------------------------------------------------
__global__ void fuse_split_weights(const float* __restrict__ W1) {
    int idx = blockIdx.x * blockDim.x + threadIdx.x;
    if (idx >= NOUT * IN_FEAT) return;
    int j = idx / IN_FEAT, k = idx % IN_FEAT;
    float w = (j < IN_FEAT) ? W1[j * NOUT + k]
                            : W1[(j - IN_FEAT) * NOUT + IN_FEAT + k];
    __nv_bfloat16 hi = __float2bfloat16(w);
    g_Whi[idx] = hi;
    g_Wlo[idx] = __float2bfloat16(w - __bfloat162float(hi));
}

// ---------------------------------------------------------------------------
// Kernel 2: node GEMM via mma.sync bf16 (HMMA), error-compensated split:
//   out = ahi*whi + alo*whi + ahi*wlo   (fp32 accumulate)
// CTA tile: M=128 x N=128, 8 warps (4 M x 2 N), warp tile 32x64.
// SMEM rows padded to 272B (17 x 16B) -> conflict-free ldmatrix.
// ---------------------------------------------------------------------------
#define AS_STRIDE 272
#define TILE_BYTES (128 * AS_STRIDE)       // 34816
#define OFF_AHI 0
#define OFF_ALO (TILE_BYTES)
#define OFF_BHI (2 * TILE_BYTES)
#define OFF_BLO (3 * TILE_BYTES)
#define SMEM_TOTAL (4 * TILE_BYTES)        // 139264

__device__ __forceinline__ void ldmx4(uint32_t addr, uint32_t& r0, uint32_t& r1,
                                      uint32_t& r2, uint32_t& r3) {
    asm volatile("ldmatrix.sync.aligned.m8n8.x4.shared.b16 {%0,%1,%2,%3}, [%4];"
                 : "=r"(r0), "=r"(r1), "=r"(r2), "=r"(r3) : "r"(addr));
}
__device__ __forceinline__ void mma_bf16(float* d, const uint32_t* a, const uint32_t* b) {
    asm volatile(
        "mma.sync.aligned.m16n8k16.row.col.f32.bf16.bf16.f32 "
        "{%0,%1,%2,%3}, {%4,%5,%6,%7}, {%8,%9}, {%0,%1,%2,%3};"
        : "+f"(d[0]), "+f"(d[1]), "+f"(d[2]), "+f"(d[3])
        : "r"(a[0]), "r"(a[1]), "r"(a[2]), "r"(a[3]), "r"(b[0]), "r"(b[1]));
}

__global__ __launch_bounds__(256, 1) void node_gemm_mma(const float* __restrict__ feat) {
    extern __shared__ __align__(16) char smem[];
    const uint32_t sb = s2u(smem);
    const int tid  = threadIdx.x;
    const int lane = tid & 31;
    const int wid  = tid >> 5;
    const int wm   = wid & 3;          // warp M index (0..3)
    const int wn   = wid >> 2;         // warp N index (0..1)
    const int row0 = blockIdx.y * 128;
    const int jcol0 = blockIdx.x * 128;  // output-column half

    // ---- load A tile (128x128 f32), split hi/lo bf16 into smem ----
    #pragma unroll
    for (int r = 0; r < 16; ++r) {
        int idx4 = r * 256 + tid;          // 4096 float4
        int row = idx4 >> 5;
        int c4  = (idx4 & 31) << 2;        // element col 0..124
        int gr = row0 + row;
        float4 v = make_float4(0.f, 0.f, 0.f, 0.f);
        if (gr < N_NODES) v = *(const float4*)(feat + (size_t)gr * IN_FEAT + c4);
        __nv_bfloat16 h0 = __float2bfloat16(v.x), h1 = __float2bfloat16(v.y);
        __nv_bfloat16 h2 = __float2bfloat16(v.z), h3 = __float2bfloat16(v.w);
        __nv_bfloat16 l0 = __float2bfloat16(v.x - __bfloat162float(h0));
        __nv_bfloat16 l1 = __float2bfloat16(v.y - __bfloat162float(h1));
        __nv_bfloat16 l2 = __float2bfloat16(v.z - __bfloat162float(h2));
        __nv_bfloat16 l3 = __float2bfloat16(v.w - __bfloat162float(h3));
        uint32_t off = row * AS_STRIDE + c4 * 2;
        *(uint2*)(smem + OFF_AHI + off) = make_uint2(pk(h0, h1), pk(h2, h3));
        *(uint2*)(smem + OFF_ALO + off) = make_uint2(pk(l0, l1), pk(l2, l3));
    }

    // ---- load B tile: 128 j-rows of Whi/Wlo (bf16, K-major) ----
    {
        const uint2* whi = (const uint2*)(g_Whi + (size_t)jcol0 * IN_FEAT);
        const uint2* wlo = (const uint2*)(g_Wlo + (size_t)jcol0 * IN_FEAT);
        #pragma unroll
        for (int r = 0; r < 16; ++r) {
            int iu = r * 256 + tid;        // 4096 uint2 (32 per row)
            int row = iu >> 5;
            int u8  = iu & 31;
            uint32_t off = row * AS_STRIDE + u8 * 8;
            *(uint2*)(smem + OFF_BHI + off) = whi[iu];
            *(uint2*)(smem + OFF_BLO + off) = wlo[iu];
        }
    }
    __syncthreads();

    // ---- accumulators: warp tile 32 (M) x 64 (N) = 2 x 8 frags x 4 f32 ----
    float acc[2][8][4];
    #pragma unroll
    for (int i = 0; i < 2; ++i)
        #pragma unroll
        for (int j = 0; j < 8; ++j)
            #pragma unroll
            for (int q = 0; q < 4; ++q) acc[i][j][q] = 0.f;

    // ldmatrix lane->address components
    const int a_row = wm * 32 + (lane & 15);          // + mt*16
    const int a_kb  = ((lane >> 4) & 1) * 16;         // 0 or 16 bytes
    const int b_row = wn * 64 + (lane & 7) + ((lane >> 4) << 3);  // +16*t
    const int b_kb  = ((lane >> 3) & 1) * 16;

    const uint32_t a_bases[2] = { sb + OFF_AHI, sb + OFF_ALO };
    const uint32_t b_bases[2] = { sb + OFF_BHI, sb + OFF_BLO };
    const int pa[3] = {0, 1, 0};   // ahi, alo, ahi
    const int pb[3] = {0, 0, 1};   // whi, whi, wlo

    #pragma unroll
    for (int pass = 0; pass < 3; ++pass) {
        const uint32_t abase = a_bases[pa[pass]];
        const uint32_t bbase = b_bases[pb[pass]];
        #pragma unroll
        for (int k0 = 0; k0 < IN_FEAT; k0 += 16) {
            const int kb = k0 * 2;
            uint32_t afr[2][4];
            #pragma unroll
            for (int mt = 0; mt < 2; ++mt)
                ldmx4(abase + (a_row + mt * 16) * AS_STRIDE + kb + a_kb,
                      afr[mt][0], afr[mt][1], afr[mt][2], afr[mt][3]);
            uint32_t bfr[8][2];
            #pragma unroll
            for (int t = 0; t < 4; ++t) {
                uint32_t r0, r1, r2, r3;
                ldmx4(bbase + (b_row + 16 * t) * AS_STRIDE + kb + b_kb, r0, r1, r2, r3);
                bfr[2 * t][0] = r0; bfr[2 * t][1] = r1;
                bfr[2 * t + 1][0] = r2; bfr[2 * t + 1][1] = r3;
            }
            #pragma unroll
            for (int mt = 0; mt < 2; ++mt)
                #pragma unroll
                for (int nt = 0; nt < 8; ++nt)
                    mma_bf16(acc[mt][nt], afr[mt], bfr[nt]);
        }
    }

    // ---- epilogue: write fp32 results straight to g_node ----
    const int gcol0 = jcol0 + wn * 64;
    #pragma unroll
    for (int mt = 0; mt < 2; ++mt) {
        const int r_lo = row0 + wm * 32 + mt * 16 + (lane >> 2);
        #pragma unroll
        for (int nt = 0; nt < 8; ++nt) {
            const int col = gcol0 + nt * 8 + (lane & 3) * 2;
            if (r_lo < N_NODES)
                *(float2*)(g_node + (size_t)r_lo * NOUT + col) =
                    make_float2(acc[mt][nt][0], acc[mt][nt][1]);
            if (r_lo + 8 < N_NODES)
                *(float2*)(g_node + (size_t)(r_lo + 8) * NOUT + col) =
                    make_float2(acc[mt][nt][2], acc[mt][nt][3]);
        }
    }
}

// ---------------------------------------------------------------------------
// Kernel 3: per-edge score. One warp per edge:
//   hid = relu(A[src] + B[dst] + b1); score = dot(hid, W2) + b2
// src/dst are int32 (JAX x64 disabled). Indices clamped defensively.
// ---------------------------------------------------------------------------
__global__ __launch_bounds__(256) void edge_score_kernel(
    const int* __restrict__ src,
    const int* __restrict__ dst,
    const float* __restrict__ b1,
    const float* __restrict__ W2,
    const float* __restrict__ b2,
    float* __restrict__ out,
    int E)
{
    const int warp = (blockIdx.x * blockDim.x + threadIdx.x) >> 5;
    const int lane = threadIdx.x & 31;
    if (warp >= E) return;

    int s = src[warp];
    int d = dst[warp];
    s = min(max(s, 0), N_NODES - 1);
    d = min(max(d, 0), N_NODES - 1);

    const float4 a = ((const float4*)(g_node + (size_t)s * NOUT))[lane];
    const float4 b = ((const float4*)(g_node + (size_t)d * NOUT + IN_FEAT))[lane];
    const float4 bias = ((const float4*)b1)[lane];
    const float4 w = ((const float4*)W2)[lane];

    const float h0 = fmaxf(a.x + b.x + bias.x, 0.f);
    const float h1 = fmaxf(a.y + b.y + bias.y, 0.f);
    const float h2 = fmaxf(a.z + b.z + bias.z, 0.f);
    const float h3 = fmaxf(a.w + b.w + bias.w, 0.f);

    float p = fmaf(h0, w.x, fmaf(h1, w.y, fmaf(h2, w.z, h3 * w.w)));

    #pragma unroll
    for (int o = 16; o; o >>= 1)
        p += __shfl_xor_sync(0xffffffffu, p, o);

    if (lane == 0) out[warp] = p + b2[0];
}

// ---------------------------------------------------------------------------
// Launch.  Inputs: 0 feature[100000,128] f32, 1 src[800000] i32,
// 2 dst[800000] i32, 3 W1[128,256] f32, 4 b1[128] f32, 5 W2[1,128] f32,
// 6 b2[1] f32.  Output: score[800000,1] f32.
// ---------------------------------------------------------------------------
extern "C" void kernel_launch(void* const* d_in, const int* in_sizes, int n_in,
                              void* d_out, int out_size) {
    const float* feat = (const float*)d_in[0];
    const int*   src  = (const int*)d_in[1];
    const int*   dst  = (const int*)d_in[2];
    const float* W1   = (const float*)d_in[3];
    const float* b1   = (const float*)d_in[4];
    const float* W2   = (const float*)d_in[5];
    const float* b2   = (const float*)d_in[6];
    float*       out  = (float*)d_out;

    const int E = in_sizes[1];

    fuse_split_weights<<<(NOUT * IN_FEAT + 255) / 256, 256>>>(W1);

    cudaFuncSetAttribute(node_gemm_mma, cudaFuncAttributeMaxDynamicSharedMemorySize, SMEM_TOTAL);
    dim3 ggrid(2, (N_NODES + 127) / 128);
    node_gemm_mma<<<ggrid, 256, SMEM_TOTAL>>>(feat);

    const int nblocks = (E + 7) / 8;
    edge_score_kernel<<<nblocks, 256>>>(src, dst, b1, W2, b2, out, E);
}

// round 8
// speedup vs baseline: 1.6063x; 1.0959x over previous
#include <cuda_runtime.h>
#include <cuda_bf16.h>
#include <cuda_fp16.h>
#include <cstdint>

#define N_NODES 100000
#define IN_FEAT 128
#define NOUT 256           // fused outputs per node: [A(128) | B(128)]

// Per-node A|B rows in fp16 (51.2 MB, L2-resident).
__device__ __half g_node[(size_t)N_NODES * NOUT];

__device__ __forceinline__ uint32_t s2u(const void* p) {
    uint32_t a;
    asm("{ .reg .u64 t; cvta.to.shared.u64 t, %1; cvt.u32.u64 %0, t; }" : "=r"(a) : "l"(p));
    return a;
}
__device__ __forceinline__ uint32_t pk(__nv_bfloat16 a, __nv_bfloat16 b) {
    __nv_bfloat162 t(a, b);
    return *reinterpret_cast<uint32_t*>(&t);
}

// ---------------------------------------------------------------------------
// Node GEMM via mma.sync bf16 (HMMA), error-compensated split:
//   out = ahi*whi + alo*whi + ahi*wlo   (fp32 accumulate, fp16 store)
// CTA tile: M=128 x N=128, 8 warps (4 M x 2 N), warp tile 32x64.
// W1 is read directly (fused layout is contiguous in k for both halves):
//   w(j,k) = W1[j & 127][ (j>=128)*128 + k ]
// SMEM rows padded to 272B (17 x 16B) -> conflict-free ldmatrix.
// ---------------------------------------------------------------------------
#define AS_STRIDE 272
#define TILE_BYTES (128 * AS_STRIDE)       // 34816
#define OFF_AHI 0
#define OFF_ALO (TILE_BYTES)
#define OFF_BHI (2 * TILE_BYTES)
#define OFF_BLO (3 * TILE_BYTES)
#define SMEM_TOTAL (4 * TILE_BYTES)        // 139264

__device__ __forceinline__ void ldmx4(uint32_t addr, uint32_t& r0, uint32_t& r1,
                                      uint32_t& r2, uint32_t& r3) {
    asm volatile("ldmatrix.sync.aligned.m8n8.x4.shared.b16 {%0,%1,%2,%3}, [%4];"
                 : "=r"(r0), "=r"(r1), "=r"(r2), "=r"(r3) : "r"(addr));
}
__device__ __forceinline__ void mma_bf16(float* d, const uint32_t* a, const uint32_t* b) {
    asm volatile(
        "mma.sync.aligned.m16n8k16.row.col.f32.bf16.bf16.f32 "
        "{%0,%1,%2,%3}, {%4,%5,%6,%7}, {%8,%9}, {%0,%1,%2,%3};"
        : "+f"(d[0]), "+f"(d[1]), "+f"(d[2]), "+f"(d[3])
        : "r"(a[0]), "r"(a[1]), "r"(a[2]), "r"(a[3]), "r"(b[0]), "r"(b[1]));
}
__device__ __forceinline__ void split4(float4 v, uint2& hi, uint2& lo) {
    __nv_bfloat16 h0 = __float2bfloat16(v.x), h1 = __float2bfloat16(v.y);
    __nv_bfloat16 h2 = __float2bfloat16(v.z), h3 = __float2bfloat16(v.w);
    __nv_bfloat16 l0 = __float2bfloat16(v.x - __bfloat162float(h0));
    __nv_bfloat16 l1 = __float2bfloat16(v.y - __bfloat162float(h1));
    __nv_bfloat16 l2 = __float2bfloat16(v.z - __bfloat162float(h2));
    __nv_bfloat16 l3 = __float2bfloat16(v.w - __bfloat162float(h3));
    hi = make_uint2(pk(h0, h1), pk(h2, h3));
    lo = make_uint2(pk(l0, l1), pk(l2, l3));
}

__global__ __launch_bounds__(256, 1) void node_gemm_mma(
    const float* __restrict__ feat, const float* __restrict__ W1)
{
    extern __shared__ __align__(16) char smem[];
    const uint32_t sb = s2u(smem);
    const int tid  = threadIdx.x;
    const int lane = tid & 31;
    const int wid  = tid >> 5;
    const int wm   = wid & 3;          // warp M index (0..3)
    const int wn   = wid >> 2;         // warp N index (0..1)
    const int row0 = blockIdx.y * 128;
    const int jcol0 = blockIdx.x * 128;  // output-column half (0: src, 128: dst)

    // ---- A tile (128x128 f32) -> hi/lo bf16 smem ----
    #pragma unroll
    for (int r = 0; r < 16; ++r) {
        int idx4 = r * 256 + tid;          // 4096 float4
        int row = idx4 >> 5;
        int c4  = (idx4 & 31) << 2;
        int gr = row0 + row;
        float4 v = make_float4(0.f, 0.f, 0.f, 0.f);
        if (gr < N_NODES) v = *(const float4*)(feat + (size_t)gr * IN_FEAT + c4);
        uint2 hi, lo;
        split4(v, hi, lo);
        uint32_t off = row * AS_STRIDE + c4 * 2;
        *(uint2*)(smem + OFF_AHI + off) = hi;
        *(uint2*)(smem + OFF_ALO + off) = lo;
    }

    // ---- B tile: W1 rows for this jcol half -> hi/lo bf16 smem ----
    {
        const float* wbase = W1 + (jcol0 ? IN_FEAT : 0);
        #pragma unroll
        for (int r = 0; r < 16; ++r) {
            int idx4 = r * 256 + tid;      // 4096 float4 (128 j x 32 float4)
            int row = idx4 >> 5;           // j_local
            int c4  = (idx4 & 31) << 2;    // k
            float4 v = *(const float4*)(wbase + (size_t)row * NOUT + c4);
            uint2 hi, lo;
            split4(v, hi, lo);
            uint32_t off = row * AS_STRIDE + c4 * 2;
            *(uint2*)(smem + OFF_BHI + off) = hi;
            *(uint2*)(smem + OFF_BLO + off) = lo;
        }
    }
    __syncthreads();

    // ---- accumulators: warp tile 32 (M) x 64 (N) = 2 x 8 frags x 4 f32 ----
    float acc[2][8][4];
    #pragma unroll
    for (int i = 0; i < 2; ++i)
        #pragma unroll
        for (int j = 0; j < 8; ++j)
            #pragma unroll
            for (int q = 0; q < 4; ++q) acc[i][j][q] = 0.f;

    const int a_row = wm * 32 + (lane & 15);
    const int a_kb  = ((lane >> 4) & 1) * 16;
    const int b_row = wn * 64 + (lane & 7) + ((lane >> 4) << 3);
    const int b_kb  = ((lane >> 3) & 1) * 16;

    const uint32_t a_bases[2] = { sb + OFF_AHI, sb + OFF_ALO };
    const uint32_t b_bases[2] = { sb + OFF_BHI, sb + OFF_BLO };
    const int pa[3] = {0, 1, 0};   // ahi, alo, ahi
    const int pb[3] = {0, 0, 1};   // whi, whi, wlo

    #pragma unroll
    for (int pass = 0; pass < 3; ++pass) {
        const uint32_t abase = a_bases[pa[pass]];
        const uint32_t bbase = b_bases[pb[pass]];
        #pragma unroll
        for (int k0 = 0; k0 < IN_FEAT; k0 += 16) {
            const int kb = k0 * 2;
            uint32_t afr[2][4];
            #pragma unroll
            for (int mt = 0; mt < 2; ++mt)
                ldmx4(abase + (a_row + mt * 16) * AS_STRIDE + kb + a_kb,
                      afr[mt][0], afr[mt][1], afr[mt][2], afr[mt][3]);
            uint32_t bfr[8][2];
            #pragma unroll
            for (int t = 0; t < 4; ++t) {
                uint32_t r0, r1, r2, r3;
                ldmx4(bbase + (b_row + 16 * t) * AS_STRIDE + kb + b_kb, r0, r1, r2, r3);
                bfr[2 * t][0] = r0; bfr[2 * t][1] = r1;
                bfr[2 * t + 1][0] = r2; bfr[2 * t + 1][1] = r3;
            }
            #pragma unroll
            for (int mt = 0; mt < 2; ++mt)
                #pragma unroll
                for (int nt = 0; nt < 8; ++nt)
                    mma_bf16(acc[mt][nt], afr[mt], bfr[nt]);
        }
    }

    // ---- epilogue: fp16 store to g_node ----
    const int gcol0 = jcol0 + wn * 64;
    #pragma unroll
    for (int mt = 0; mt < 2; ++mt) {
        const int r_lo = row0 + wm * 32 + mt * 16 + (lane >> 2);
        #pragma unroll
        for (int nt = 0; nt < 8; ++nt) {
            const int col = gcol0 + nt * 8 + (lane & 3) * 2;
            if (r_lo < N_NODES)
                *(__half2*)(g_node + (size_t)r_lo * NOUT + col) =
                    __floats2half2_rn(acc[mt][nt][0], acc[mt][nt][1]);
            if (r_lo + 8 < N_NODES)
                *(__half2*)(g_node + (size_t)(r_lo + 8) * NOUT + col) =
                    __floats2half2_rn(acc[mt][nt][2], acc[mt][nt][3]);
        }
    }
}

// ---------------------------------------------------------------------------
// Edge score. One warp per edge:
//   hid = relu(A[src] + B[dst] + b1); score = dot(hid, W2) + b2
// A/B rows are fp16 (8B per lane per row). Math in fp32.
// ---------------------------------------------------------------------------
__global__ __launch_bounds__(256) void edge_score_kernel(
    const int* __restrict__ src,
    const int* __restrict__ dst,
    const float* __restrict__ b1,
    const float* __restrict__ W2,
    const float* __restrict__ b2,
    float* __restrict__ out,
    int E)
{
    const int warp = (blockIdx.x * blockDim.x + threadIdx.x) >> 5;
    const int lane = threadIdx.x & 31;
    if (warp >= E) return;

    int s = src[warp];
    int d = dst[warp];
    s = min(max(s, 0), N_NODES - 1);
    d = min(max(d, 0), N_NODES - 1);

    const uint2 ua = *(const uint2*)(g_node + (size_t)s * NOUT + lane * 4);
    const uint2 ub = *(const uint2*)(g_node + (size_t)d * NOUT + IN_FEAT + lane * 4);
    const float4 bias = ((const float4*)b1)[lane];
    const float4 w = ((const float4*)W2)[lane];

    const float2 a01 = __half22float2(*reinterpret_cast<const __half2*>(&ua.x));
    const float2 a23 = __half22float2(*reinterpret_cast<const __half2*>(&ua.y));
    const float2 b01 = __half22float2(*reinterpret_cast<const __half2*>(&ub.x));
    const float2 b23 = __half22float2(*reinterpret_cast<const __half2*>(&ub.y));

    const float h0 = fmaxf(a01.x + b01.x + bias.x, 0.f);
    const float h1 = fmaxf(a01.y + b01.y + bias.y, 0.f);
    const float h2 = fmaxf(a23.x + b23.x + bias.z, 0.f);
    const float h3 = fmaxf(a23.y + b23.y + bias.w, 0.f);

    float p = fmaf(h0, w.x, fmaf(h1, w.y, fmaf(h2, w.z, h3 * w.w)));

    #pragma unroll
    for (int o = 16; o; o >>= 1)
        p += __shfl_xor_sync(0xffffffffu, p, o);

    if (lane == 0) out[warp] = p + b2[0];
}

// ---------------------------------------------------------------------------
// Launch.  Inputs: 0 feature[100000,128] f32, 1 src[800000] i32,
// 2 dst[800000] i32, 3 W1[128,256] f32, 4 b1[128] f32, 5 W2[1,128] f32,
// 6 b2[1] f32.  Output: score[800000,1] f32.
// ---------------------------------------------------------------------------
extern "C" void kernel_launch(void* const* d_in, const int* in_sizes, int n_in,
                              void* d_out, int out_size) {
    const float* feat = (const float*)d_in[0];
    const int*   src  = (const int*)d_in[1];
    const int*   dst  = (const int*)d_in[2];
    const float* W1   = (const float*)d_in[3];
    const float* b1   = (const float*)d_in[4];
    const float* W2   = (const float*)d_in[5];
    const float* b2   = (const float*)d_in[6];
    float*       out  = (float*)d_out;

    const int E = in_sizes[1];

    cudaFuncSetAttribute(node_gemm_mma, cudaFuncAttributeMaxDynamicSharedMemorySize, SMEM_TOTAL);
    dim3 ggrid(2, (N_NODES + 127) / 128);
    node_gemm_mma<<<ggrid, 256, SMEM_TOTAL>>>(feat, W1);

    const int nblocks = (E + 7) / 8;
    edge_score_kernel<<<nblocks, 256>>>(src, dst, b1, W2, b2, out, E);
}

// round 9
// speedup vs baseline: 2.2144x; 1.3786x over previous
#include <cuda_runtime.h>
#include <cuda_bf16.h>
#include <cuda_fp16.h>
#include <cstdint>

#define N_NODES 100000
#define IN_FEAT 128
#define NOUT 256           // fused outputs per node: [A(128) | B(128)]

// Per-node A|B rows in fp16 (51.2 MB, L2-resident) + pre-split bf16 weights.
__device__ __half g_node[(size_t)N_NODES * NOUT];
__device__ __align__(16) __nv_bfloat16 g_Whi[NOUT * IN_FEAT];   // [j][k] K-major
__device__ __align__(16) __nv_bfloat16 g_Wlo[NOUT * IN_FEAT];

__device__ __forceinline__ uint32_t s2u(const void* p) {
    uint32_t a;
    asm("{ .reg .u64 t; cvta.to.shared.u64 t, %1; cvt.u32.u64 %0, t; }" : "=r"(a) : "l"(p));
    return a;
}
__device__ __forceinline__ uint32_t pk(__nv_bfloat16 a, __nv_bfloat16 b) {
    __nv_bfloat162 t(a, b);
    return *reinterpret_cast<uint32_t*>(&t);
}

// ---------------------------------------------------------------------------
// Kernel 1: fuse + transpose + bf16-split W1 (128x256 row-major) -> Whi/Wlo[j][k]
//   j<128: W1[j,k] (src half);  j>=128: W1[j-128, 128+k] (dst half)
// ---------------------------------------------------------------------------
__global__ void fuse_split_weights(const float* __restrict__ W1) {
    int idx = blockIdx.x * blockDim.x + threadIdx.x;
    if (idx >= NOUT * IN_FEAT) return;
    int j = idx / IN_FEAT, k = idx % IN_FEAT;
    float w = (j < IN_FEAT) ? W1[j * NOUT + k]
                            : W1[(j - IN_FEAT) * NOUT + IN_FEAT + k];
    __nv_bfloat16 hi = __float2bfloat16(w);
    g_Whi[idx] = hi;
    g_Wlo[idx] = __float2bfloat16(w - __bfloat162float(hi));
}

// ---------------------------------------------------------------------------
// Kernel 2: node GEMM via mma.sync bf16 (HMMA), error-compensated split:
//   out = ahi*whi + alo*whi + ahi*wlo   (fp32 accumulate, fp16 store)
// CTA tile: M=128 x N=256 (full output), 8 warps as 2M x 4N, warp tile 64x64.
// A tile loaded+split ONCE per CTA; W loaded pre-split (bf16).
// SMEM rows padded to 272B (17 x 16B) -> conflict-free ldmatrix.
// ---------------------------------------------------------------------------
#define AS_STRIDE 272
#define A_TILE_B (128 * AS_STRIDE)         // 34816
#define B_TILE_B (256 * AS_STRIDE)         // 69632
#define OFF_AHI 0
#define OFF_ALO (A_TILE_B)
#define OFF_BHI (2 * A_TILE_B)
#define OFF_BLO (2 * A_TILE_B + B_TILE_B)
#define SMEM_TOTAL (2 * A_TILE_B + 2 * B_TILE_B)   // 208896

__device__ __forceinline__ void ldmx4(uint32_t addr, uint32_t& r0, uint32_t& r1,
                                      uint32_t& r2, uint32_t& r3) {
    asm volatile("ldmatrix.sync.aligned.m8n8.x4.shared.b16 {%0,%1,%2,%3}, [%4];"
                 : "=r"(r0), "=r"(r1), "=r"(r2), "=r"(r3) : "r"(addr));
}
__device__ __forceinline__ void mma_bf16(float* d, const uint32_t* a, const uint32_t* b) {
    asm volatile(
        "mma.sync.aligned.m16n8k16.row.col.f32.bf16.bf16.f32 "
        "{%0,%1,%2,%3}, {%4,%5,%6,%7}, {%8,%9}, {%0,%1,%2,%3};"
        : "+f"(d[0]), "+f"(d[1]), "+f"(d[2]), "+f"(d[3])
        : "r"(a[0]), "r"(a[1]), "r"(a[2]), "r"(a[3]), "r"(b[0]), "r"(b[1]));
}
__device__ __forceinline__ void split4(float4 v, uint2& hi, uint2& lo) {
    __nv_bfloat16 h0 = __float2bfloat16(v.x), h1 = __float2bfloat16(v.y);
    __nv_bfloat16 h2 = __float2bfloat16(v.z), h3 = __float2bfloat16(v.w);
    __nv_bfloat16 l0 = __float2bfloat16(v.x - __bfloat162float(h0));
    __nv_bfloat16 l1 = __float2bfloat16(v.y - __bfloat162float(h1));
    __nv_bfloat16 l2 = __float2bfloat16(v.z - __bfloat162float(h2));
    __nv_bfloat16 l3 = __float2bfloat16(v.w - __bfloat162float(h3));
    hi = make_uint2(pk(h0, h1), pk(h2, h3));
    lo = make_uint2(pk(l0, l1), pk(l2, l3));
}

__global__ __launch_bounds__(256, 1) void node_gemm_mma(const float* __restrict__ feat) {
    extern __shared__ __align__(16) char smem[];
    const uint32_t sb = s2u(smem);
    const int tid  = threadIdx.x;
    const int lane = tid & 31;
    const int wid  = tid >> 5;
    const int wm   = wid & 1;          // warp M index (0..1), tile 64 rows
    const int wn   = wid >> 1;         // warp N index (0..3), tile 64 cols
    const int row0 = blockIdx.x * 128;

    // ---- A tile (128x128 f32) -> hi/lo bf16 smem (once per CTA) ----
    #pragma unroll
    for (int r = 0; r < 16; ++r) {
        int idx4 = r * 256 + tid;          // 4096 float4
        int row = idx4 >> 5;
        int c4  = (idx4 & 31) << 2;
        int gr = row0 + row;
        float4 v = make_float4(0.f, 0.f, 0.f, 0.f);
        if (gr < N_NODES) v = *(const float4*)(feat + (size_t)gr * IN_FEAT + c4);
        uint2 hi, lo;
        split4(v, hi, lo);
        uint32_t off = row * AS_STRIDE + c4 * 2;
        *(uint2*)(smem + OFF_AHI + off) = hi;
        *(uint2*)(smem + OFF_ALO + off) = lo;
    }

    // ---- B tiles: pre-split bf16 weights, all 256 j-rows ----
    {
        const uint4* whi = (const uint4*)g_Whi;   // 4096 uint4, 16 per row
        const uint4* wlo = (const uint4*)g_Wlo;
        #pragma unroll
        for (int r = 0; r < 16; ++r) {
            int iu = r * 256 + tid;        // 0..4095
            int row = iu >> 4;             // 0..255
            int u16 = iu & 15;
            uint32_t off = row * AS_STRIDE + u16 * 16;
            *(uint4*)(smem + OFF_BHI + off) = whi[iu];
            *(uint4*)(smem + OFF_BLO + off) = wlo[iu];
        }
    }
    __syncthreads();

    // ---- accumulators: warp tile 64x64 = 4 mt x 8 nt frags x 4 f32 ----
    float acc[4][8][4];
    #pragma unroll
    for (int i = 0; i < 4; ++i)
        #pragma unroll
        for (int j = 0; j < 8; ++j)
            #pragma unroll
            for (int q = 0; q < 4; ++q) acc[i][j][q] = 0.f;

    const int a_row = wm * 64 + (lane & 15);
    const int a_kb  = ((lane >> 4) & 1) * 16;
    const int b_row = wn * 64 + (lane & 7) + ((lane >> 4) << 3);
    const int b_kb  = ((lane >> 3) & 1) * 16;

    const uint32_t a_bases[2] = { sb + OFF_AHI, sb + OFF_ALO };
    const uint32_t b_bases[2] = { sb + OFF_BHI, sb + OFF_BLO };
    const int pa[3] = {0, 1, 0};   // ahi, alo, ahi
    const int pb[3] = {0, 0, 1};   // whi, whi, wlo

    #pragma unroll
    for (int pass = 0; pass < 3; ++pass) {
        const uint32_t abase = a_bases[pa[pass]];
        const uint32_t bbase = b_bases[pb[pass]];
        #pragma unroll
        for (int k0 = 0; k0 < IN_FEAT; k0 += 16) {
            const int kb = k0 * 2;
            uint32_t afr[4][4];
            #pragma unroll
            for (int mt = 0; mt < 4; ++mt)
                ldmx4(abase + (a_row + mt * 16) * AS_STRIDE + kb + a_kb,
                      afr[mt][0], afr[mt][1], afr[mt][2], afr[mt][3]);
            uint32_t bfr[8][2];
            #pragma unroll
            for (int t = 0; t < 4; ++t) {
                uint32_t r0, r1, r2, r3;
                ldmx4(bbase + (b_row + 16 * t) * AS_STRIDE + kb + b_kb, r0, r1, r2, r3);
                bfr[2 * t][0] = r0; bfr[2 * t][1] = r1;
                bfr[2 * t + 1][0] = r2; bfr[2 * t + 1][1] = r3;
            }
            #pragma unroll
            for (int mt = 0; mt < 4; ++mt)
                #pragma unroll
                for (int nt = 0; nt < 8; ++nt)
                    mma_bf16(acc[mt][nt], afr[mt], bfr[nt]);
        }
    }

    // ---- epilogue: fp16 store to g_node ----
    const int gcol0 = wn * 64;
    #pragma unroll
    for (int mt = 0; mt < 4; ++mt) {
        const int r_lo = row0 + wm * 64 + mt * 16 + (lane >> 2);
        #pragma unroll
        for (int nt = 0; nt < 8; ++nt) {
            const int col = gcol0 + nt * 8 + (lane & 3) * 2;
            if (r_lo < N_NODES)
                *(__half2*)(g_node + (size_t)r_lo * NOUT + col) =
                    __floats2half2_rn(acc[mt][nt][0], acc[mt][nt][1]);
            if (r_lo + 8 < N_NODES)
                *(__half2*)(g_node + (size_t)(r_lo + 8) * NOUT + col) =
                    __floats2half2_rn(acc[mt][nt][2], acc[mt][nt][3]);
        }
    }
}

// ---------------------------------------------------------------------------
// Kernel 3: edge score, 16 edges per warp.
//   hid = relu(A[src] + B[dst] + b1); score = dot(hid, W2) + b2
// Constants (b1/W2/b2) register-resident; indices batch-loaded coalesced and
// broadcast via shuffle; butterfly reduce leaves sum in all lanes so lane e
// keeps edge e -> one coalesced 16-lane store per warp.
// ---------------------------------------------------------------------------
#define EPW 16

__global__ __launch_bounds__(256) void edge_score_kernel(
    const int* __restrict__ src,
    const int* __restrict__ dst,
    const float* __restrict__ b1,
    const float* __restrict__ W2,
    const float* __restrict__ b2,
    float* __restrict__ out,
    int E)
{
    const int warp = (blockIdx.x * blockDim.x + threadIdx.x) >> 5;
    const int lane = threadIdx.x & 31;
    const int base = warp * EPW;
    if (base >= E) return;

    const float4 bias = ((const float4*)b1)[lane];
    const float4 w = ((const float4*)W2)[lane];
    const float bb = b2[0];

    // lanes 0..15 -> src[base..base+15], lanes 16..31 -> dst[base..base+15]
    const int eidx = base + (lane & 15);
    int node = 0;
    if (eidx < E) node = (lane < 16) ? src[eidx] : dst[eidx];
    node = min(max(node, 0), N_NODES - 1);
    // byte offset into g_node (fits 32-bit: 51.2 MB)
    uint32_t off = (uint32_t)node * (NOUT * 2) + ((lane >= 16) ? (IN_FEAT * 2) : 0);

    const char* gbase = (const char*)g_node;
    const uint32_t lb = lane * 8;
    float res = 0.f;

    #pragma unroll
    for (int e = 0; e < EPW; ++e) {
        const uint32_t so = __shfl_sync(0xffffffffu, off, e);
        const uint32_t dofs = __shfl_sync(0xffffffffu, off, 16 + e);
        const uint2 ua = *(const uint2*)(gbase + so + lb);
        const uint2 ub = *(const uint2*)(gbase + dofs + lb);

        const float2 a01 = __half22float2(*reinterpret_cast<const __half2*>(&ua.x));
        const float2 a23 = __half22float2(*reinterpret_cast<const __half2*>(&ua.y));
        const float2 b01 = __half22float2(*reinterpret_cast<const __half2*>(&ub.x));
        const float2 b23 = __half22float2(*reinterpret_cast<const __half2*>(&ub.y));

        const float h0 = fmaxf(a01.x + b01.x + bias.x, 0.f);
        const float h1 = fmaxf(a01.y + b01.y + bias.y, 0.f);
        const float h2 = fmaxf(a23.x + b23.x + bias.z, 0.f);
        const float h3 = fmaxf(a23.y + b23.y + bias.w, 0.f);

        float p = fmaf(h0, w.x, fmaf(h1, w.y, fmaf(h2, w.z, h3 * w.w)));
        #pragma unroll
        for (int o = 16; o; o >>= 1)
            p += __shfl_xor_sync(0xffffffffu, p, o);

        if (lane == e) res = p + bb;     // lane e owns edge e's result
    }

    if (lane < 16 && base + lane < E) out[base + lane] = res;
}

// ---------------------------------------------------------------------------
// Launch.  Inputs: 0 feature[100000,128] f32, 1 src[800000] i32,
// 2 dst[800000] i32, 3 W1[128,256] f32, 4 b1[128] f32, 5 W2[1,128] f32,
// 6 b2[1] f32.  Output: score[800000,1] f32.
// ---------------------------------------------------------------------------
extern "C" void kernel_launch(void* const* d_in, const int* in_sizes, int n_in,
                              void* d_out, int out_size) {
    const float* feat = (const float*)d_in[0];
    const int*   src  = (const int*)d_in[1];
    const int*   dst  = (const int*)d_in[2];
    const float* W1   = (const float*)d_in[3];
    const float* b1   = (const float*)d_in[4];
    const float* W2   = (const float*)d_in[5];
    const float* b2   = (const float*)d_in[6];
    float*       out  = (float*)d_out;

    const int E = in_sizes[1];

    fuse_split_weights<<<(NOUT * IN_FEAT + 255) / 256, 256>>>(W1);

    cudaFuncSetAttribute(node_gemm_mma, cudaFuncAttributeMaxDynamicSharedMemorySize, SMEM_TOTAL);
    node_gemm_mma<<<(N_NODES + 127) / 128, 256, SMEM_TOTAL>>>(feat);

    const int warps = (E + EPW - 1) / EPW;            // 50000
    const int nblocks = (warps + 7) / 8;              // 6250 blocks of 256 thr
    edge_score_kernel<<<nblocks, 256>>>(src, dst, b1, W2, b2, out, E);
}

// round 12
// speedup vs baseline: 2.3878x; 1.0783x over previous
#include <cuda_runtime.h>
#include <cuda_bf16.h>
#include <cuda_fp16.h>
#include <cstdint>

#define N_NODES 100000
#define IN_FEAT 128
#define NOUT 256           // fused outputs per node: [A(128) | B(128)]

// Per-node A|B rows in fp16 (51.2 MB, L2-resident) + pre-split bf16 weights.
__device__ __half g_node[(size_t)N_NODES * NOUT];
__device__ __align__(16) __nv_bfloat16 g_Whi[NOUT * IN_FEAT];   // [j][k] K-major
__device__ __align__(16) __nv_bfloat16 g_Wlo[NOUT * IN_FEAT];

__device__ __forceinline__ uint32_t s2u(const void* p) {
    uint32_t a;
    asm("{ .reg .u64 t; cvta.to.shared.u64 t, %1; cvt.u32.u64 %0, t; }" : "=r"(a) : "l"(p));
    return a;
}
__device__ __forceinline__ uint32_t pk(__nv_bfloat16 a, __nv_bfloat16 b) {
    __nv_bfloat162 t(a, b);
    return *reinterpret_cast<uint32_t*>(&t);
}

// ---------------------------------------------------------------------------
// Kernel 1: fuse + transpose + bf16-split W1 (128x256 row-major) -> Whi/Wlo[j][k]
// ---------------------------------------------------------------------------
__global__ void fuse_split_weights(const float* __restrict__ W1) {
    int idx = blockIdx.x * blockDim.x + threadIdx.x;
    if (idx >= NOUT * IN_FEAT) return;
    int j = idx / IN_FEAT, k = idx % IN_FEAT;
    float w = (j < IN_FEAT) ? W1[j * NOUT + k]
                            : W1[(j - IN_FEAT) * NOUT + IN_FEAT + k];
    __nv_bfloat16 hi = __float2bfloat16(w);
    g_Whi[idx] = hi;
    g_Wlo[idx] = __float2bfloat16(w - __bfloat162float(hi));
}

// ---------------------------------------------------------------------------
// Kernel 2: node GEMM via mma.sync bf16 (HMMA), error-compensated split,
// K split into two 64-wide chunks, pipelined:
//   cp.async B(c0), B(c1); LDG+split+STS A(c0); LDG A(c1) [regs];
//   wait B(c0) -> mma chunk0 (overlaps B(c1)/A(c1) arrival) ->
//   split+STS A(c1) -> wait -> mma chunk1 -> epilogue.
// CTA tile M=128 x N=256, 8 warps (2M x 4N), warp tile 64x64.
// Chunk tiles: rows x 64 cols bf16, row stride 144B (conflict-free ldmatrix).
// ---------------------------------------------------------------------------
#define CH_STRIDE 144
#define A_CH_B (128 * CH_STRIDE)          // 18432
#define B_CH_B (256 * CH_STRIDE)          // 36864
#define A_BASE 0
#define B_BASE (4 * A_CH_B)               // 73728
#define SMEM_TOTAL (B_BASE + 4 * B_CH_B)  // 221184
// A tile (hl, c): A_BASE + c*2*A_CH_B + hl*A_CH_B   (hl: 0=hi, 1=lo)
// B tile (hl, c): B_BASE + c*2*B_CH_B + hl*B_CH_B

#define CP_ASYNC16(sdst, gsrc) \
    asm volatile("cp.async.cg.shared.global [%0], [%1], 16;" :: "r"(sdst), "l"(gsrc))
#define CP_COMMIT() asm volatile("cp.async.commit_group;")
#define CP_WAIT(n)  asm volatile("cp.async.wait_group %0;" :: "n"(n))

__device__ __forceinline__ void ldmx4(uint32_t addr, uint32_t& r0, uint32_t& r1,
                                      uint32_t& r2, uint32_t& r3) {
    asm volatile("ldmatrix.sync.aligned.m8n8.x4.shared.b16 {%0,%1,%2,%3}, [%4];"
                 : "=r"(r0), "=r"(r1), "=r"(r2), "=r"(r3) : "r"(addr));
}
__device__ __forceinline__ void mma_bf16(float* d, const uint32_t* a, const uint32_t* b) {
    asm volatile(
        "mma.sync.aligned.m16n8k16.row.col.f32.bf16.bf16.f32 "
        "{%0,%1,%2,%3}, {%4,%5,%6,%7}, {%8,%9}, {%0,%1,%2,%3};"
        : "+f"(d[0]), "+f"(d[1]), "+f"(d[2]), "+f"(d[3])
        : "r"(a[0]), "r"(a[1]), "r"(a[2]), "r"(a[3]), "r"(b[0]), "r"(b[1]));
}
__device__ __forceinline__ void split4(float4 v, uint2& hi, uint2& lo) {
    __nv_bfloat16 h0 = __float2bfloat16(v.x), h1 = __float2bfloat16(v.y);
    __nv_bfloat16 h2 = __float2bfloat16(v.z), h3 = __float2bfloat16(v.w);
    __nv_bfloat16 l0 = __float2bfloat16(v.x - __bfloat162float(h0));
    __nv_bfloat16 l1 = __float2bfloat16(v.y - __bfloat162float(h1));
    __nv_bfloat16 l2 = __float2bfloat16(v.z - __bfloat162float(h2));
    __nv_bfloat16 l3 = __float2bfloat16(v.w - __bfloat162float(h3));
    hi = make_uint2(pk(h0, h1), pk(h2, h3));
    lo = make_uint2(pk(l0, l1), pk(l2, l3));
}

__global__ __launch_bounds__(256, 1) void node_gemm_mma(const float* __restrict__ feat) {
    extern __shared__ __align__(16) char smem[];
    const uint32_t sb = s2u(smem);
    const int tid  = threadIdx.x;
    const int lane = tid & 31;
    const int wid  = tid >> 5;
    const int wm   = wid & 1;          // warp M index (0..1), 64 rows
    const int wn   = wid >> 1;         // warp N index (0..3), 64 cols
    const int row0 = blockIdx.x * 128;

    // ---- issue cp.async for B, chunk 0 then chunk 1 (separate groups) ----
    #pragma unroll
    for (int c = 0; c < 2; ++c) {
        #pragma unroll
        for (int hl = 0; hl < 2; ++hl) {
            const char* gsrc = (const char*)(hl ? g_Wlo : g_Whi);
            const uint32_t sdst = sb + B_BASE + c * 2 * B_CH_B + hl * B_CH_B;
            #pragma unroll
            for (int r = 0; r < 8; ++r) {
                int iu = r * 256 + tid;      // 0..2047
                int row = iu >> 3;           // 0..255
                int col = iu & 7;            // 16B unit
                CP_ASYNC16(sdst + row * CH_STRIDE + col * 16,
                           gsrc + row * 256 + c * 128 + col * 16);
            }
        }
        CP_COMMIT();
    }

    // ---- A chunk 0: LDG -> split -> STS ----
    {
        #pragma unroll
        for (int r = 0; r < 8; ++r) {
            int idx4 = r * 256 + tid;        // 2048 float4 (chunk = 128x64 f32)
            int row = idx4 >> 4;             // 16 float4 per row
            int c4  = (idx4 & 15) << 2;      // col 0..60
            int gr = row0 + row;
            float4 v = make_float4(0.f, 0.f, 0.f, 0.f);
            if (gr < N_NODES) v = *(const float4*)(feat + (size_t)gr * IN_FEAT + c4);
            uint2 hi, lo;
            split4(v, hi, lo);
            uint32_t off = row * CH_STRIDE + c4 * 2;
            *(uint2*)(smem + A_BASE + off) = hi;             // hi, c0
            *(uint2*)(smem + A_BASE + A_CH_B + off) = lo;    // lo, c0
        }
    }

    // ---- A chunk 1: issue LDGs now, keep in regs through mma chunk0 ----
    float4 a1[8];
    #pragma unroll
    for (int r = 0; r < 8; ++r) {
        int idx4 = r * 256 + tid;
        int row = idx4 >> 4;
        int c4  = (idx4 & 15) << 2;
        int gr = row0 + row;
        a1[r] = make_float4(0.f, 0.f, 0.f, 0.f);
        if (gr < N_NODES) a1[r] = *(const float4*)(feat + (size_t)gr * IN_FEAT + 64 + c4);
    }

    // ---- accumulators: warp tile 64x64 = 4 mt x 8 nt frags x 4 f32 ----
    float acc[4][8][4];
    #pragma unroll
    for (int i = 0; i < 4; ++i)
        #pragma unroll
        for (int j = 0; j < 8; ++j)
            #pragma unroll
            for (int q = 0; q < 4; ++q) acc[i][j][q] = 0.f;

    const int a_row = wm * 64 + (lane & 15);
    const int a_kb  = ((lane >> 4) & 1) * 16;
    const int b_row = wn * 64 + (lane & 7) + ((lane >> 4) << 3);
    const int b_kb  = ((lane >> 3) & 1) * 16;
    const int pa[3] = {0, 1, 0};   // ahi, alo, ahi
    const int pb[3] = {0, 0, 1};   // whi, whi, wlo

    // mma over one K-chunk: 3 passes x 4 k-steps of 16
    auto mma_chunk = [&](int c) {
        #pragma unroll
        for (int pass = 0; pass < 3; ++pass) {
            const uint32_t abase = sb + A_BASE + c * 2 * A_CH_B + pa[pass] * A_CH_B;
            const uint32_t bbase = sb + B_BASE + c * 2 * B_CH_B + pb[pass] * B_CH_B;
            #pragma unroll
            for (int ks = 0; ks < 4; ++ks) {
                const int kb = ks * 32;
                uint32_t afr[4][4];
                #pragma unroll
                for (int mt = 0; mt < 4; ++mt)
                    ldmx4(abase + (a_row + mt * 16) * CH_STRIDE + kb + a_kb,
                          afr[mt][0], afr[mt][1], afr[mt][2], afr[mt][3]);
                uint32_t bfr[8][2];
                #pragma unroll
                for (int t = 0; t < 4; ++t) {
                    uint32_t r0, r1, r2, r3;
                    ldmx4(bbase + (b_row + 16 * t) * CH_STRIDE + kb + b_kb,
                          r0, r1, r2, r3);
                    bfr[2 * t][0] = r0; bfr[2 * t][1] = r1;
                    bfr[2 * t + 1][0] = r2; bfr[2 * t + 1][1] = r3;
                }
                #pragma unroll
                for (int mt = 0; mt < 4; ++mt)
                    #pragma unroll
                    for (int nt = 0; nt < 8; ++nt)
                        mma_bf16(acc[mt][nt], afr[mt], bfr[nt]);
            }
        }
    };

    CP_WAIT(1);            // B chunk0 resident
    __syncthreads();       // + A chunk0 STS visible

    mma_chunk(0);

    // ---- A chunk 1: split -> STS (LDGs long since issued) ----
    #pragma unroll
    for (int r = 0; r < 8; ++r) {
        int idx4 = r * 256 + tid;
        int row = idx4 >> 4;
        int c4  = (idx4 & 15) << 2;
        uint2 hi, lo;
        split4(a1[r], hi, lo);
        uint32_t off = row * CH_STRIDE + c4 * 2;
        *(uint2*)(smem + A_BASE + 2 * A_CH_B + off) = hi;           // hi, c1
        *(uint2*)(smem + A_BASE + 3 * A_CH_B + off) = lo;           // lo, c1
    }

    CP_WAIT(0);            // B chunk1 resident
    __syncthreads();

    mma_chunk(1);

    // ---- epilogue: fp16 store to g_node ----
    const int gcol0 = wn * 64;
    #pragma unroll
    for (int mt = 0; mt < 4; ++mt) {
        const int r_lo = row0 + wm * 64 + mt * 16 + (lane >> 2);
        #pragma unroll
        for (int nt = 0; nt < 8; ++nt) {
            const int col = gcol0 + nt * 8 + (lane & 3) * 2;
            if (r_lo < N_NODES)
                *(__half2*)(g_node + (size_t)r_lo * NOUT + col) =
                    __floats2half2_rn(acc[mt][nt][0], acc[mt][nt][1]);
            if (r_lo + 8 < N_NODES)
                *(__half2*)(g_node + (size_t)(r_lo + 8) * NOUT + col) =
                    __floats2half2_rn(acc[mt][nt][2], acc[mt][nt][3]);
        }
    }
}

// ---------------------------------------------------------------------------
// Kernel 3: edge score, 16 edges/warp, 2 edges per round (16 lanes each).
//   hid = relu(A[src] + B[dst] + b1); score = dot(hid, W2) + b2
// uint4 loads (8 fp16/lane), group-half butterfly reduce (4 shfl / 2 edges),
// one fix-up shfl, coalesced 16-lane store.
// ---------------------------------------------------------------------------
__device__ __forceinline__ float2 h2f(uint32_t u) {
    return __half22float2(*reinterpret_cast<const __half2*>(&u));
}

__global__ __launch_bounds__(256) void edge_score_kernel(
    const int* __restrict__ src,
    const int* __restrict__ dst,
    const float* __restrict__ b1,
    const float* __restrict__ W2,
    const float* __restrict__ b2,
    float* __restrict__ out,
    int E)
{
    const int warp = (blockIdx.x * blockDim.x + threadIdx.x) >> 5;
    const int lane = threadIdx.x & 31;
    const int base = warp * 16;
    if (base >= E) return;

    const int l15 = lane & 15;
    const float4 bias0 = ((const float4*)b1)[l15 * 2];
    const float4 bias1 = ((const float4*)b1)[l15 * 2 + 1];
    const float4 w0 = ((const float4*)W2)[l15 * 2];
    const float4 w1 = ((const float4*)W2)[l15 * 2 + 1];
    const float bb = b2[0];

    // lanes 0..15 hold src offsets of edges base..base+15; lanes 16..31 dst.
    const int eidx = base + l15;
    int node = 0;
    if (eidx < E) node = (lane < 16) ? src[eidx] : dst[eidx];
    node = min(max(node, 0), N_NODES - 1);
    uint32_t off = (uint32_t)node * (NOUT * 2) + ((lane >= 16) ? (IN_FEAT * 2) : 0);

    const char* gbase = (const char*)g_node;
    const int g = lane >> 4;           // group: 0 -> even edge, 1 -> odd edge
    float res = 0.f;

    #pragma unroll
    for (int r = 0; r < 8; ++r) {
        const int e = 2 * r + g;
        const uint32_t so = __shfl_sync(0xffffffffu, off, e);
        const uint32_t dofs = __shfl_sync(0xffffffffu, off, 16 + e);
        const uint4 ua = *(const uint4*)(gbase + so + l15 * 16);
        const uint4 ub = *(const uint4*)(gbase + dofs + l15 * 16);

        const float2 a0 = h2f(ua.x), a1 = h2f(ua.y), a2 = h2f(ua.z), a3 = h2f(ua.w);
        const float2 c0 = h2f(ub.x), c1 = h2f(ub.y), c2 = h2f(ub.z), c3 = h2f(ub.w);

        const float h0 = fmaxf(a0.x + c0.x + bias0.x, 0.f);
        const float h1 = fmaxf(a0.y + c0.y + bias0.y, 0.f);
        const float h2_ = fmaxf(a1.x + c1.x + bias0.z, 0.f);
        const float h3 = fmaxf(a1.y + c1.y + bias0.w, 0.f);
        const float h4 = fmaxf(a2.x + c2.x + bias1.x, 0.f);
        const float h5 = fmaxf(a2.y + c2.y + bias1.y, 0.f);
        const float h6 = fmaxf(a3.x + c3.x + bias1.z, 0.f);
        const float h7 = fmaxf(a3.y + c3.y + bias1.w, 0.f);

        float p = fmaf(h0, w0.x, fmaf(h1, w0.y, fmaf(h2_, w0.z, h3 * w0.w)));
        p = fmaf(h4, w1.x, fmaf(h5, w1.y, fmaf(h6, w1.z, fmaf(h7, w1.w, p))));

        // reduce within each 16-lane half (edges stay separate)
        #pragma unroll
        for (int o = 8; o; o >>= 1)
            p += __shfl_xor_sync(0xffffffffu, p, o);

        // keeper lanes: even edge -> lane 2r (group 0); odd edge -> lane 17+2r (group 1)
        if (lane == 2 * r + 17 * g) res = p + bb;
    }

    // odd-edge results live in lanes 17,19,...,31; pull them down to 1,3,...,15
    const float other = __shfl_sync(0xffffffffu, res, (lane + 16) & 31);
    const float val = (lane & 1) ? other : res;
    if (lane < 16 && base + lane < E) out[base + lane] = val;
}

// ---------------------------------------------------------------------------
// Launch.  Inputs: 0 feature[100000,128] f32, 1 src[800000] i32,
// 2 dst[800000] i32, 3 W1[128,256] f32, 4 b1[128] f32, 5 W2[1,128] f32,
// 6 b2[1] f32.  Output: score[800000,1] f32.
// ---------------------------------------------------------------------------
extern "C" void kernel_launch(void* const* d_in, const int* in_sizes, int n_in,
                              void* d_out, int out_size) {
    const float* feat = (const float*)d_in[0];
    const int*   src  = (const int*)d_in[1];
    const int*   dst  = (const int*)d_in[2];
    const float* W1   = (const float*)d_in[3];
    const float* b1   = (const float*)d_in[4];
    const float* W2   = (const float*)d_in[5];
    const float* b2   = (const float*)d_in[6];
    float*       out  = (float*)d_out;

    const int E = in_sizes[1];

    fuse_split_weights<<<(NOUT * IN_FEAT + 255) / 256, 256>>>(W1);

    cudaFuncSetAttribute(node_gemm_mma, cudaFuncAttributeMaxDynamicSharedMemorySize, SMEM_TOTAL);
    node_gemm_mma<<<(N_NODES + 127) / 128, 256, SMEM_TOTAL>>>(feat);

    const int nblocks = (E + 127) / 128;   // 8 warps x 16 edges per block
    edge_score_kernel<<<nblocks, 256>>>(src, dst, b1, W2, b2, out, E);
}

// round 13
// speedup vs baseline: 2.7255x; 1.1414x over previous
#include <cuda_runtime.h>
#include <cuda_bf16.h>
#include <cuda_fp16.h>
#include <cstdint>

#define N_NODES 100000
#define IN_FEAT 128
#define NOUT 256           // fused outputs per node: [A(128) | B(128)]

// Per-node A|B rows in fp16 (51.2 MB, L2-resident) + pre-split bf16 weights.
__device__ __half g_node[(size_t)N_NODES * NOUT];
__device__ __align__(16) __nv_bfloat16 g_Whi[NOUT * IN_FEAT];   // [j][k] K-major
__device__ __align__(16) __nv_bfloat16 g_Wlo[NOUT * IN_FEAT];
__device__ float g_zero[IN_FEAT];   // zero-initialized (.bss) — bias for B-half CTAs

__device__ __forceinline__ uint32_t s2u(const void* p) {
    uint32_t a;
    asm("{ .reg .u64 t; cvta.to.shared.u64 t, %1; cvt.u32.u64 %0, t; }" : "=r"(a) : "l"(p));
    return a;
}
__device__ __forceinline__ uint32_t pk(__nv_bfloat16 a, __nv_bfloat16 b) {
    __nv_bfloat162 t(a, b);
    return *reinterpret_cast<uint32_t*>(&t);
}

// ---------------------------------------------------------------------------
// Kernel 1: fuse + transpose + bf16-split W1 (128x256 row-major) -> Whi/Wlo[j][k]
// ---------------------------------------------------------------------------
__global__ void fuse_split_weights(const float* __restrict__ W1) {
    int idx = blockIdx.x * blockDim.x + threadIdx.x;
    if (idx >= NOUT * IN_FEAT) return;
    int j = idx / IN_FEAT, k = idx % IN_FEAT;
    float w = (j < IN_FEAT) ? W1[j * NOUT + k]
                            : W1[(j - IN_FEAT) * NOUT + IN_FEAT + k];
    __nv_bfloat16 hi = __float2bfloat16(w);
    g_Whi[idx] = hi;
    g_Wlo[idx] = __float2bfloat16(w - __bfloat162float(hi));
}

// ---------------------------------------------------------------------------
// Kernel 2: node GEMM via mma.sync bf16 (HMMA), error-compensated split
//   out = ahi*whi + alo*whi + ahi*wlo   (fp32 accumulate, +bias, fp16 store)
// CTA tile M=128 x N=128; K as four 32-wide chunks, double-buffered (2 stages
// x hi/lo for both A and B) -> 80 KB smem -> 2 CTAs/SM. 8 warps (2M x 4N),
// warp tile 64x32 (64 acc regs). Row stride 80B: conflict-free ldmatrix
// (8 consecutive rows at 80B stride cover the 8 distinct 16B units mod 128).
// ---------------------------------------------------------------------------
#define CH2 80
#define A_CH 10240                 // 128 rows * 80B
#define B_CH 10240                 // 128 rows * 80B
#define SM_A 0                     // A[stage][hl] at (stage*2+hl)*A_CH
#define SM_B (4 * A_CH)            // B[stage][hl] at SM_B + (stage*2+hl)*B_CH
#define SMEM_TOTAL (SM_B + 4 * B_CH)   // 81920

#define CP_ASYNC16(sdst, gsrc) \
    asm volatile("cp.async.cg.shared.global [%0], [%1], 16;" :: "r"(sdst), "l"(gsrc))
#define CP_COMMIT() asm volatile("cp.async.commit_group;")
#define CP_WAIT(n)  asm volatile("cp.async.wait_group %0;" :: "n"(n))

__device__ __forceinline__ void ldmx4(uint32_t addr, uint32_t& r0, uint32_t& r1,
                                      uint32_t& r2, uint32_t& r3) {
    asm volatile("ldmatrix.sync.aligned.m8n8.x4.shared.b16 {%0,%1,%2,%3}, [%4];"
                 : "=r"(r0), "=r"(r1), "=r"(r2), "=r"(r3) : "r"(addr));
}
__device__ __forceinline__ void mma_bf16(float* d, const uint32_t* a, const uint32_t* b) {
    asm volatile(
        "mma.sync.aligned.m16n8k16.row.col.f32.bf16.bf16.f32 "
        "{%0,%1,%2,%3}, {%4,%5,%6,%7}, {%8,%9}, {%0,%1,%2,%3};"
        : "+f"(d[0]), "+f"(d[1]), "+f"(d[2]), "+f"(d[3])
        : "r"(a[0]), "r"(a[1]), "r"(a[2]), "r"(a[3]), "r"(b[0]), "r"(b[1]));
}
__device__ __forceinline__ void split4(float4 v, uint2& hi, uint2& lo) {
    __nv_bfloat16 h0 = __float2bfloat16(v.x), h1 = __float2bfloat16(v.y);
    __nv_bfloat16 h2 = __float2bfloat16(v.z), h3 = __float2bfloat16(v.w);
    __nv_bfloat16 l0 = __float2bfloat16(v.x - __bfloat162float(h0));
    __nv_bfloat16 l1 = __float2bfloat16(v.y - __bfloat162float(h1));
    __nv_bfloat16 l2 = __float2bfloat16(v.z - __bfloat162float(h2));
    __nv_bfloat16 l3 = __float2bfloat16(v.w - __bfloat162float(h3));
    hi = make_uint2(pk(h0, h1), pk(h2, h3));
    lo = make_uint2(pk(l0, l1), pk(l2, l3));
}

__global__ __launch_bounds__(256, 2) void node_gemm_mma(
    const float* __restrict__ feat, const float* __restrict__ b1)
{
    extern __shared__ __align__(16) char smem[];
    const uint32_t sb = s2u(smem);
    const int tid  = threadIdx.x;
    const int lane = tid & 31;
    const int wid  = tid >> 5;
    const int wm   = wid & 1;            // 64-row warp band
    const int wn   = wid >> 1;           // 32-col warp band (0..3)
    const int row0  = blockIdx.y * 128;
    const int jcol0 = blockIdx.x * 128;  // 0: src/A half (biased), 128: dst/B half

    // ---- helpers ----
    // A chunk c: 128 rows x 32 f32 cols -> 4 float4 per thread
    auto ldgA = [&](int c, float4* rA) {
        #pragma unroll
        for (int r = 0; r < 4; ++r) {
            int idx4 = r * 256 + tid;          // 1024 float4
            int row = idx4 >> 3;               // 8 f4 per row
            int c4  = (idx4 & 7) << 2;
            int gr = row0 + row;
            rA[r] = make_float4(0.f, 0.f, 0.f, 0.f);
            if (gr < N_NODES)
                rA[r] = *(const float4*)(feat + (size_t)gr * IN_FEAT + c * 32 + c4);
        }
    };
    auto stsA = [&](int st, const float4* rA) {
        #pragma unroll
        for (int r = 0; r < 4; ++r) {
            int idx4 = r * 256 + tid;
            int row = idx4 >> 3;
            int c4  = (idx4 & 7) << 2;
            uint2 hi, lo;
            split4(rA[r], hi, lo);
            uint32_t off = row * CH2 + c4 * 2;
            *(uint2*)(smem + SM_A + (st * 2 + 0) * A_CH + off) = hi;
            *(uint2*)(smem + SM_A + (st * 2 + 1) * A_CH + off) = lo;
        }
    };
    auto cpB = [&](int c, int st) {
        #pragma unroll
        for (int hl = 0; hl < 2; ++hl) {
            const char* gsrc = (const char*)(hl ? g_Wlo : g_Whi);
            const uint32_t sdst = sb + SM_B + (st * 2 + hl) * B_CH;
            #pragma unroll
            for (int r = 0; r < 2; ++r) {
                int iu = r * 256 + tid;        // 512 16B units
                int row = iu >> 2;             // 0..127
                int u   = iu & 3;
                CP_ASYNC16(sdst + row * CH2 + u * 16,
                           gsrc + (size_t)(jcol0 + row) * 256 + c * 64 + u * 16);
            }
        }
        CP_COMMIT();
    };

    // ---- accumulators: warp tile 64x32 = 4 mt x 4 nt frags x 4 f32 ----
    float acc[4][4][4];
    #pragma unroll
    for (int i = 0; i < 4; ++i)
        #pragma unroll
        for (int j = 0; j < 4; ++j)
            #pragma unroll
            for (int q = 0; q < 4; ++q) acc[i][j][q] = 0.f;

    const int a_row = wm * 64 + (lane & 15);
    const int a_kb  = ((lane >> 4) & 1) * 16;
    const int b_row = wn * 32 + (lane & 7) + ((lane >> 4) << 3);
    const int b_kb  = ((lane >> 3) & 1) * 16;
    const int pa[3] = {0, 1, 0};   // ahi, alo, ahi
    const int pb[3] = {0, 0, 1};   // whi, whi, wlo

    auto mma_st = [&](int st) {
        const uint32_t abase = sb + SM_A + st * 2 * A_CH;
        const uint32_t bbase = sb + SM_B + st * 2 * B_CH;
        #pragma unroll
        for (int pass = 0; pass < 3; ++pass) {
            const uint32_t ab = abase + pa[pass] * A_CH;
            const uint32_t bb = bbase + pb[pass] * B_CH;
            #pragma unroll
            for (int ks = 0; ks < 2; ++ks) {
                const int kb = ks * 32;
                uint32_t afr[4][4];
                #pragma unroll
                for (int mt = 0; mt < 4; ++mt)
                    ldmx4(ab + (a_row + mt * 16) * CH2 + kb + a_kb,
                          afr[mt][0], afr[mt][1], afr[mt][2], afr[mt][3]);
                uint32_t bfr[4][2];
                #pragma unroll
                for (int t = 0; t < 2; ++t) {
                    uint32_t r0, r1, r2, r3;
                    ldmx4(bb + (b_row + 16 * t) * CH2 + kb + b_kb, r0, r1, r2, r3);
                    bfr[2 * t][0] = r0; bfr[2 * t][1] = r1;
                    bfr[2 * t + 1][0] = r2; bfr[2 * t + 1][1] = r3;
                }
                #pragma unroll
                for (int mt = 0; mt < 4; ++mt)
                    #pragma unroll
                    for (int nt = 0; nt < 4; ++nt)
                        mma_bf16(acc[mt][nt], afr[mt], bfr[nt]);
            }
        }
    };

    // ---- pipeline: 4 chunks, 2 stages ----
    float4 rA[4];
    ldgA(0, rA);
    cpB(0, 0);
    cpB(1, 1);
    stsA(0, rA);
    ldgA(1, rA);

    CP_WAIT(1);                 // B chunk0 resident
    __syncthreads();
    mma_st(0);
    stsA(1, rA);
    ldgA(2, rA);

    CP_WAIT(0);                 // B chunk1 resident
    __syncthreads();            // all warps done with stage0
    cpB(2, 0);
    mma_st(1);
    stsA(0, rA);                // A chunk2 -> stage0
    ldgA(3, rA);

    CP_WAIT(0);                 // B chunk2 resident
    __syncthreads();
    cpB(3, 1);
    mma_st(0);
    stsA(1, rA);                // A chunk3 -> stage1

    CP_WAIT(0);                 // B chunk3 resident
    __syncthreads();
    mma_st(1);

    // ---- epilogue: +bias (A-half only), fp16 store ----
    const float* bias = (jcol0 == 0) ? b1 : g_zero;
    #pragma unroll
    for (int mt = 0; mt < 4; ++mt) {
        const int r_lo = row0 + wm * 64 + mt * 16 + (lane >> 2);
        #pragma unroll
        for (int nt = 0; nt < 4; ++nt) {
            const int lcol = wn * 32 + nt * 8 + (lane & 3) * 2;
            const float2 bv = *(const float2*)(bias + lcol);
            const int gcol = jcol0 + lcol;
            if (r_lo < N_NODES)
                *(__half2*)(g_node + (size_t)r_lo * NOUT + gcol) =
                    __floats2half2_rn(acc[mt][nt][0] + bv.x, acc[mt][nt][1] + bv.y);
            if (r_lo + 8 < N_NODES)
                *(__half2*)(g_node + (size_t)(r_lo + 8) * NOUT + gcol) =
                    __floats2half2_rn(acc[mt][nt][2] + bv.x, acc[mt][nt][3] + bv.y);
        }
    }
}

// ---------------------------------------------------------------------------
// Kernel 3: edge score, 16 edges/warp, 2 edges per round (16 lanes each).
// Bias is pre-folded into g_node's A half, so: hid = relu(A[src] + B[dst]);
// score = dot(hid, W2) + b2.
// ---------------------------------------------------------------------------
__device__ __forceinline__ float2 h2f(uint32_t u) {
    return __half22float2(*reinterpret_cast<const __half2*>(&u));
}

__global__ __launch_bounds__(256) void edge_score_kernel(
    const int* __restrict__ src,
    const int* __restrict__ dst,
    const float* __restrict__ W2,
    const float* __restrict__ b2,
    float* __restrict__ out,
    int E)
{
    const int warp = (blockIdx.x * blockDim.x + threadIdx.x) >> 5;
    const int lane = threadIdx.x & 31;
    const int base = warp * 16;
    if (base >= E) return;

    const int l15 = lane & 15;
    const float4 w0 = ((const float4*)W2)[l15 * 2];
    const float4 w1 = ((const float4*)W2)[l15 * 2 + 1];
    const float bb = b2[0];

    const int eidx = base + l15;
    int node = 0;
    if (eidx < E) node = (lane < 16) ? src[eidx] : dst[eidx];
    node = min(max(node, 0), N_NODES - 1);
    uint32_t off = (uint32_t)node * (NOUT * 2) + ((lane >= 16) ? (IN_FEAT * 2) : 0);

    const char* gbase = (const char*)g_node;
    const int g = lane >> 4;           // group: 0 -> even edge, 1 -> odd edge
    float res = 0.f;

    #pragma unroll
    for (int r = 0; r < 8; ++r) {
        const int e = 2 * r + g;
        const uint32_t so = __shfl_sync(0xffffffffu, off, e);
        const uint32_t dofs = __shfl_sync(0xffffffffu, off, 16 + e);
        const uint4 ua = *(const uint4*)(gbase + so + l15 * 16);
        const uint4 ub = *(const uint4*)(gbase + dofs + l15 * 16);

        const float2 a0 = h2f(ua.x), a1 = h2f(ua.y), a2 = h2f(ua.z), a3 = h2f(ua.w);
        const float2 c0 = h2f(ub.x), c1 = h2f(ub.y), c2 = h2f(ub.z), c3 = h2f(ub.w);

        const float h0 = fmaxf(a0.x + c0.x, 0.f);
        const float h1 = fmaxf(a0.y + c0.y, 0.f);
        const float h2_ = fmaxf(a1.x + c1.x, 0.f);
        const float h3 = fmaxf(a1.y + c1.y, 0.f);
        const float h4 = fmaxf(a2.x + c2.x, 0.f);
        const float h5 = fmaxf(a2.y + c2.y, 0.f);
        const float h6 = fmaxf(a3.x + c3.x, 0.f);
        const float h7 = fmaxf(a3.y + c3.y, 0.f);

        float p = fmaf(h0, w0.x, fmaf(h1, w0.y, fmaf(h2_, w0.z, h3 * w0.w)));
        p = fmaf(h4, w1.x, fmaf(h5, w1.y, fmaf(h6, w1.z, fmaf(h7, w1.w, p))));

        #pragma unroll
        for (int o = 8; o; o >>= 1)
            p += __shfl_xor_sync(0xffffffffu, p, o);

        if (lane == 2 * r + 17 * g) res = p + bb;
    }

    const float other = __shfl_sync(0xffffffffu, res, (lane + 16) & 31);
    const float val = (lane & 1) ? other : res;
    if (lane < 16 && base + lane < E) out[base + lane] = val;
}

// ---------------------------------------------------------------------------
// Launch.  Inputs: 0 feature[100000,128] f32, 1 src[800000] i32,
// 2 dst[800000] i32, 3 W1[128,256] f32, 4 b1[128] f32, 5 W2[1,128] f32,
// 6 b2[1] f32.  Output: score[800000,1] f32.
// ---------------------------------------------------------------------------
extern "C" void kernel_launch(void* const* d_in, const int* in_sizes, int n_in,
                              void* d_out, int out_size) {
    const float* feat = (const float*)d_in[0];
    const int*   src  = (const int*)d_in[1];
    const int*   dst  = (const int*)d_in[2];
    const float* W1   = (const float*)d_in[3];
    const float* b1   = (const float*)d_in[4];
    const float* W2   = (const float*)d_in[5];
    const float* b2   = (const float*)d_in[6];
    float*       out  = (float*)d_out;

    const int E = in_sizes[1];

    fuse_split_weights<<<(NOUT * IN_FEAT + 255) / 256, 256>>>(W1);

    cudaFuncSetAttribute(node_gemm_mma, cudaFuncAttributeMaxDynamicSharedMemorySize, SMEM_TOTAL);
    dim3 ggrid(2, (N_NODES + 127) / 128);
    node_gemm_mma<<<ggrid, 256, SMEM_TOTAL>>>(feat, b1);

    const int nblocks = (E + 127) / 128;   // 8 warps x 16 edges per block
    edge_score_kernel<<<nblocks, 256>>>(src, dst, W2, b2, out, E);
}

// round 14
// speedup vs baseline: 2.8474x; 1.0447x over previous
#include <cuda_runtime.h>
#include <cuda_bf16.h>
#include <cuda_fp16.h>
#include <cstdint>

#define N_NODES 100000
#define IN_FEAT 128
#define NOUT 256           // fused outputs per node: [A(128) | B(128)]
#define NTILES 782         // ceil(100000/128)

// Per-node A|B rows in fp16 (51.2 MB, L2-resident).
__device__ __half g_node[(size_t)N_NODES * NOUT];
__device__ float g_zero[IN_FEAT];   // zero bias for the B half

__device__ __forceinline__ uint32_t s2u(const void* p) {
    uint32_t a;
    asm("{ .reg .u64 t; cvta.to.shared.u64 t, %1; cvt.u32.u64 %0, t; }" : "=r"(a) : "l"(p));
    return a;
}
__device__ __forceinline__ uint32_t pk(__nv_bfloat16 a, __nv_bfloat16 b) {
    __nv_bfloat162 t(a, b);
    return *reinterpret_cast<uint32_t*>(&t);
}

// ---------------------------------------------------------------------------
// Persistent node GEMM via mma.sync bf16 (HMMA), error-compensated split:
//   out = ahi*whi + alo*whi + ahi*wlo   (fp32 accumulate, +bias, fp16 store)
// 296 CTAs (2/SM). Each CTA: jhalf = bid&1 (0 => W1[:, :128]^T src half with
// bias b1; 1 => W1[:, 128:]^T dst half, bias 0). Init: split its 128x128 W1
// block to bf16 hi/lo in smem ONCE (stride 272, conflict-free ldmatrix).
// Then loop row-tiles rt = (bid>>1) + 148*it, streaming A (fp32->hi/lo bf16)
// through a 2-stage, 32-col-chunk double buffer (stride 80, conflict-free).
// 8 warps (2M x 4N), warp tile 64x32.
// ---------------------------------------------------------------------------
#define CH2 80
#define A_CH 10240                  // 128 rows * 80B
#define SM_A 0                      // A[stage][hl] at (stage*2+hl)*A_CH
#define BSTRIDE 272
#define B_HALF (128 * BSTRIDE)      // 34816
#define SM_B (4 * A_CH)             // 40960; Bhi at SM_B, Blo at SM_B+B_HALF
#define SMEM_TOTAL (SM_B + 2 * B_HALF)   // 110592

__device__ __forceinline__ void ldmx4(uint32_t addr, uint32_t& r0, uint32_t& r1,
                                      uint32_t& r2, uint32_t& r3) {
    asm volatile("ldmatrix.sync.aligned.m8n8.x4.shared.b16 {%0,%1,%2,%3}, [%4];"
                 : "=r"(r0), "=r"(r1), "=r"(r2), "=r"(r3) : "r"(addr));
}
__device__ __forceinline__ void mma_bf16(float* d, const uint32_t* a, const uint32_t* b) {
    asm volatile(
        "mma.sync.aligned.m16n8k16.row.col.f32.bf16.bf16.f32 "
        "{%0,%1,%2,%3}, {%4,%5,%6,%7}, {%8,%9}, {%0,%1,%2,%3};"
        : "+f"(d[0]), "+f"(d[1]), "+f"(d[2]), "+f"(d[3])
        : "r"(a[0]), "r"(a[1]), "r"(a[2]), "r"(a[3]), "r"(b[0]), "r"(b[1]));
}
__device__ __forceinline__ void split4(float4 v, uint2& hi, uint2& lo) {
    __nv_bfloat16 h0 = __float2bfloat16(v.x), h1 = __float2bfloat16(v.y);
    __nv_bfloat16 h2 = __float2bfloat16(v.z), h3 = __float2bfloat16(v.w);
    __nv_bfloat16 l0 = __float2bfloat16(v.x - __bfloat162float(h0));
    __nv_bfloat16 l1 = __float2bfloat16(v.y - __bfloat162float(h1));
    __nv_bfloat16 l2 = __float2bfloat16(v.z - __bfloat162float(h2));
    __nv_bfloat16 l3 = __float2bfloat16(v.w - __bfloat162float(h3));
    hi = make_uint2(pk(h0, h1), pk(h2, h3));
    lo = make_uint2(pk(l0, l1), pk(l2, l3));
}

__global__ __launch_bounds__(256, 2) void node_gemm_mma(
    const float* __restrict__ feat, const float* __restrict__ W1,
    const float* __restrict__ b1)
{
    extern __shared__ __align__(16) char smem[];
    const uint32_t sb = s2u(smem);
    const int tid  = threadIdx.x;
    const int lane = tid & 31;
    const int wid  = tid >> 5;
    const int wm   = wid & 1;            // 64-row warp band
    const int wn   = wid >> 1;           // 32-col warp band (0..3)
    const int bid  = blockIdx.x;
    const int jhalf = bid & 1;
    const int jcol0 = jhalf * 128;

    // ---- init: split this CTA's W1 block into resident Bhi/Blo smem ----
    // w(j_local, k) = W1[j_local][jhalf*128 + k]
    #pragma unroll
    for (int r = 0; r < 16; ++r) {
        int idx4 = r * 256 + tid;            // 4096 float4 (128 j x 32 f4)
        int jl = idx4 >> 5;
        int c4 = (idx4 & 31) << 2;
        float4 v = *(const float4*)(W1 + (size_t)jl * NOUT + jhalf * 128 + c4);
        uint2 hi, lo;
        split4(v, hi, lo);
        uint32_t off = jl * BSTRIDE + c4 * 2;
        *(uint2*)(smem + SM_B + off) = hi;
        *(uint2*)(smem + SM_B + B_HALF + off) = lo;
    }
    __syncthreads();

    // ---- lane mappings ----
    const int a_row = wm * 64 + (lane & 15);
    const int a_kb  = ((lane >> 4) & 1) * 16;
    const int b_row = wn * 32 + (lane & 7) + ((lane >> 4) << 3);
    const int b_kb  = ((lane >> 3) & 1) * 16;
    const int pa[3] = {0, 1, 0};   // ahi, alo, ahi
    const int pb[3] = {0, 0, 1};   // whi, whi, wlo
    const float* bias = jhalf ? g_zero : b1;

    // ---- tile loop ----
    for (int it = 0; it < 6; ++it) {
        const int rt = (bid >> 1) + it * 148;
        if (rt >= NTILES) break;
        const int row0 = rt * 128;

        // A chunk load (32 f32 cols) -> 4 float4 per thread
        auto ldgA = [&](int c, float4* rA) {
            #pragma unroll
            for (int r = 0; r < 4; ++r) {
                int idx4 = r * 256 + tid;
                int row = idx4 >> 3;
                int c4  = (idx4 & 7) << 2;
                int gr = row0 + row;
                rA[r] = make_float4(0.f, 0.f, 0.f, 0.f);
                if (gr < N_NODES)
                    rA[r] = *(const float4*)(feat + (size_t)gr * IN_FEAT + c * 32 + c4);
            }
        };
        auto stsA = [&](int st, const float4* rA) {
            #pragma unroll
            for (int r = 0; r < 4; ++r) {
                int idx4 = r * 256 + tid;
                int row = idx4 >> 3;
                int c4  = (idx4 & 7) << 2;
                uint2 hi, lo;
                split4(rA[r], hi, lo);
                uint32_t off = row * CH2 + c4 * 2;
                *(uint2*)(smem + SM_A + (st * 2 + 0) * A_CH + off) = hi;
                *(uint2*)(smem + SM_A + (st * 2 + 1) * A_CH + off) = lo;
            }
        };

        float acc[4][4][4];
        #pragma unroll
        for (int i = 0; i < 4; ++i)
            #pragma unroll
            for (int j = 0; j < 4; ++j)
                #pragma unroll
                for (int q = 0; q < 4; ++q) acc[i][j][q] = 0.f;

        // mma over one A stage against resident B, K-chunk kc (32 wide)
        auto mma_st = [&](int st, int kc) {
            const uint32_t abase = sb + SM_A + st * 2 * A_CH;
            const uint32_t bbase = sb + SM_B;
            #pragma unroll
            for (int pass = 0; pass < 3; ++pass) {
                const uint32_t ab = abase + pa[pass] * A_CH;
                const uint32_t bbh = bbase + pb[pass] * B_HALF;
                #pragma unroll
                for (int ks = 0; ks < 2; ++ks) {
                    const int akb = ks * 32;
                    const int bkb = kc * 64 + ks * 32;
                    uint32_t afr[4][4];
                    #pragma unroll
                    for (int mt = 0; mt < 4; ++mt)
                        ldmx4(ab + (a_row + mt * 16) * CH2 + akb + a_kb,
                              afr[mt][0], afr[mt][1], afr[mt][2], afr[mt][3]);
                    uint32_t bfr[4][2];
                    #pragma unroll
                    for (int t = 0; t < 2; ++t) {
                        uint32_t r0, r1, r2, r3;
                        ldmx4(bbh + (b_row + 16 * t) * BSTRIDE + bkb + b_kb,
                              r0, r1, r2, r3);
                        bfr[2 * t][0] = r0; bfr[2 * t][1] = r1;
                        bfr[2 * t + 1][0] = r2; bfr[2 * t + 1][1] = r3;
                    }
                    #pragma unroll
                    for (int mt = 0; mt < 4; ++mt)
                        #pragma unroll
                        for (int nt = 0; nt < 4; ++nt)
                            mma_bf16(acc[mt][nt], afr[mt], bfr[nt]);
                }
            }
        };

        // pipeline: 4 A chunks, 2 stages
        float4 rA[4];
        ldgA(0, rA);
        stsA(0, rA);
        ldgA(1, rA);

        __syncthreads();
        mma_st(0, 0);
        stsA(1, rA);
        ldgA(2, rA);

        __syncthreads();
        mma_st(1, 1);
        stsA(0, rA);
        ldgA(3, rA);

        __syncthreads();
        mma_st(0, 2);
        stsA(1, rA);

        __syncthreads();
        mma_st(1, 3);

        // epilogue: +bias, fp16 store
        #pragma unroll
        for (int mt = 0; mt < 4; ++mt) {
            const int r_lo = row0 + wm * 64 + mt * 16 + (lane >> 2);
            #pragma unroll
            for (int nt = 0; nt < 4; ++nt) {
                const int lcol = wn * 32 + nt * 8 + (lane & 3) * 2;
                const float2 bv = *(const float2*)(bias + lcol);
                const int gcol = jcol0 + lcol;
                if (r_lo < N_NODES)
                    *(__half2*)(g_node + (size_t)r_lo * NOUT + gcol) =
                        __floats2half2_rn(acc[mt][nt][0] + bv.x, acc[mt][nt][1] + bv.y);
                if (r_lo + 8 < N_NODES)
                    *(__half2*)(g_node + (size_t)(r_lo + 8) * NOUT + gcol) =
                        __floats2half2_rn(acc[mt][nt][2] + bv.x, acc[mt][nt][3] + bv.y);
            }
        }
        // NOTE: next iteration's stsA(0) touches stage0, last read at this
        // tile's mma_st(0, 2) which is fenced by the __syncthreads above
        // mma_st(1, 3) — no extra barrier needed.
    }
}

// ---------------------------------------------------------------------------
// Edge score, 16 edges/warp, 2 edges per round (16 lanes each).
// Bias pre-folded into g_node's A half: hid = relu_h2(A[src] + B[dst]);
// score = dot(hid, W2) + b2 (dot in fp32).
// ---------------------------------------------------------------------------
__device__ __forceinline__ __half2 h2(uint32_t u) {
    return *reinterpret_cast<const __half2*>(&u);
}

__global__ __launch_bounds__(256) void edge_score_kernel(
    const int* __restrict__ src,
    const int* __restrict__ dst,
    const float* __restrict__ W2,
    const float* __restrict__ b2,
    float* __restrict__ out,
    int E)
{
    const int warp = (blockIdx.x * blockDim.x + threadIdx.x) >> 5;
    const int lane = threadIdx.x & 31;
    const int base = warp * 16;
    if (base >= E) return;

    const int l15 = lane & 15;
    const float4 w0 = ((const float4*)W2)[l15 * 2];
    const float4 w1 = ((const float4*)W2)[l15 * 2 + 1];
    const float bb = b2[0];
    const __half2 z2 = __float2half2_rn(0.f);

    const int eidx = base + l15;
    int node = 0;
    if (eidx < E) node = (lane < 16) ? src[eidx] : dst[eidx];
    node = min(max(node, 0), N_NODES - 1);
    uint32_t off = (uint32_t)node * (NOUT * 2) + ((lane >= 16) ? (IN_FEAT * 2) : 0);

    const char* gbase = (const char*)g_node;
    const int g = lane >> 4;           // group: 0 -> even edge, 1 -> odd edge
    float res = 0.f;

    #pragma unroll
    for (int r = 0; r < 8; ++r) {
        const int e = 2 * r + g;
        const uint32_t so = __shfl_sync(0xffffffffu, off, e);
        const uint32_t dofs = __shfl_sync(0xffffffffu, off, 16 + e);
        const uint4 ua = *(const uint4*)(gbase + so + l15 * 16);
        const uint4 ub = *(const uint4*)(gbase + dofs + l15 * 16);

        const __half2 s0 = __hmax2(__hadd2(h2(ua.x), h2(ub.x)), z2);
        const __half2 s1 = __hmax2(__hadd2(h2(ua.y), h2(ub.y)), z2);
        const __half2 s2 = __hmax2(__hadd2(h2(ua.z), h2(ub.z)), z2);
        const __half2 s3 = __hmax2(__hadd2(h2(ua.w), h2(ub.w)), z2);

        const float2 f0 = __half22float2(s0);
        const float2 f1 = __half22float2(s1);
        const float2 f2 = __half22float2(s2);
        const float2 f3 = __half22float2(s3);

        float p = fmaf(f0.x, w0.x, fmaf(f0.y, w0.y, fmaf(f1.x, w0.z, f1.y * w0.w)));
        p = fmaf(f2.x, w1.x, fmaf(f2.y, w1.y, fmaf(f3.x, w1.z, fmaf(f3.y, w1.w, p))));

        #pragma unroll
        for (int o = 8; o; o >>= 1)
            p += __shfl_xor_sync(0xffffffffu, p, o);

        if (lane == 2 * r + 17 * g) res = p + bb;
    }

    const float other = __shfl_sync(0xffffffffu, res, (lane + 16) & 31);
    const float val = (lane & 1) ? other : res;
    if (lane < 16 && base + lane < E) out[base + lane] = val;
}

// ---------------------------------------------------------------------------
// Launch.  Inputs: 0 feature[100000,128] f32, 1 src[800000] i32,
// 2 dst[800000] i32, 3 W1[128,256] f32, 4 b1[128] f32, 5 W2[1,128] f32,
// 6 b2[1] f32.  Output: score[800000,1] f32.
// ---------------------------------------------------------------------------
extern "C" void kernel_launch(void* const* d_in, const int* in_sizes, int n_in,
                              void* d_out, int out_size) {
    const float* feat = (const float*)d_in[0];
    const int*   src  = (const int*)d_in[1];
    const int*   dst  = (const int*)d_in[2];
    const float* W1   = (const float*)d_in[3];
    const float* b1   = (const float*)d_in[4];
    const float* W2   = (const float*)d_in[5];
    const float* b2   = (const float*)d_in[6];
    float*       out  = (float*)d_out;

    const int E = in_sizes[1];

    cudaFuncSetAttribute(node_gemm_mma, cudaFuncAttributeMaxDynamicSharedMemorySize, SMEM_TOTAL);
    node_gemm_mma<<<296, 256, SMEM_TOTAL>>>(feat, W1, b1);

    const int nblocks = (E + 127) / 128;   // 8 warps x 16 edges per block
    edge_score_kernel<<<nblocks, 256>>>(src, dst, W2, b2, out, E);
}

// round 15
// speedup vs baseline: 3.3553x; 1.1783x over previous
#include <cuda_runtime.h>
#include <cuda_bf16.h>
#include <cuda_fp16.h>
#include <cstdint>

#define N_NODES 100000
#define IN_FEAT 128
#define NOUT 256           // fused outputs per node: [A(128) | B(128)]
#define NTILES 782         // ceil(100000/128)

// Per-node A|B rows in fp16 (51.2 MB, L2-resident).
__device__ __half g_node[(size_t)N_NODES * NOUT];
__device__ float g_zero[IN_FEAT];   // zero bias for the B half

__device__ __forceinline__ uint32_t s2u(const void* p) {
    uint32_t a;
    asm("{ .reg .u64 t; cvta.to.shared.u64 t, %1; cvt.u32.u64 %0, t; }" : "=r"(a) : "l"(p));
    return a;
}
__device__ __forceinline__ uint32_t pkh(__half a, __half b) {
    __half2 t(a, b);
    return *reinterpret_cast<uint32_t*>(&t);
}

// ---------------------------------------------------------------------------
// Persistent node GEMM via mma.sync fp16 (HMMA), W-split compensation:
//   out = a_f16 * w_hi + a_f16 * w_lo   (fp32 accumulate, +bias, fp16 store)
// w_hi = fp16(w), w_lo = fp16(w - w_hi): W quantization error ~2^-22 (negligible);
// only A's fp16 rounding (~2.8e-4 RMS) enters the result.
// 296 CTAs (2/SM). jhalf = bid&1 selects W1[:, :128] (src, bias b1) or
// W1[:, 128:] (dst, bias 0). W block split once into resident smem (stride
// 272, conflict-free ldmatrix). Row-tiles rt = (bid>>1) + 148*it stream A as
// four 32-col chunks through a 2-stage fp16 buffer (stride 80, conflict-free).
// 8 warps (2M x 4N), warp tile 64x32.
// ---------------------------------------------------------------------------
#define CH2 80
#define A_CH 10240                  // 128 rows * 80B (fp16, single copy)
#define SM_A 0                      // A[stage] at st*A_CH
#define BSTRIDE 272
#define B_HALF (128 * BSTRIDE)      // 34816
#define SM_B (2 * A_CH)             // 20480; Whi at SM_B, Wlo at SM_B+B_HALF
#define SMEM_TOTAL (SM_B + 2 * B_HALF)   // 90112

__device__ __forceinline__ void ldmx4(uint32_t addr, uint32_t& r0, uint32_t& r1,
                                      uint32_t& r2, uint32_t& r3) {
    asm volatile("ldmatrix.sync.aligned.m8n8.x4.shared.b16 {%0,%1,%2,%3}, [%4];"
                 : "=r"(r0), "=r"(r1), "=r"(r2), "=r"(r3) : "r"(addr));
}
__device__ __forceinline__ void mma_f16(float* d, const uint32_t* a, const uint32_t* b) {
    asm volatile(
        "mma.sync.aligned.m16n8k16.row.col.f32.f16.f16.f32 "
        "{%0,%1,%2,%3}, {%4,%5,%6,%7}, {%8,%9}, {%0,%1,%2,%3};"
        : "+f"(d[0]), "+f"(d[1]), "+f"(d[2]), "+f"(d[3])
        : "r"(a[0]), "r"(a[1]), "r"(a[2]), "r"(a[3]), "r"(b[0]), "r"(b[1]));
}

__global__ __launch_bounds__(256, 2) void node_gemm_mma(
    const float* __restrict__ feat, const float* __restrict__ W1,
    const float* __restrict__ b1)
{
    extern __shared__ __align__(16) char smem[];
    const uint32_t sb = s2u(smem);
    const int tid  = threadIdx.x;
    const int lane = tid & 31;
    const int wid  = tid >> 5;
    const int wm   = wid & 1;            // 64-row warp band
    const int wn   = wid >> 1;           // 32-col warp band (0..3)
    const int bid  = blockIdx.x;
    const int jhalf = bid & 1;
    const int jcol0 = jhalf * 128;

    // ---- init: fp16-split this CTA's W1 block into resident smem ----
    // w(jl, k) = W1[jl][jhalf*128 + k]
    #pragma unroll
    for (int r = 0; r < 16; ++r) {
        int idx4 = r * 256 + tid;            // 4096 float4 (128 j x 32 f4)
        int jl = idx4 >> 5;
        int c4 = (idx4 & 31) << 2;
        float4 v = *(const float4*)(W1 + (size_t)jl * NOUT + jhalf * 128 + c4);
        __half h0 = __float2half_rn(v.x), h1 = __float2half_rn(v.y);
        __half h2 = __float2half_rn(v.z), h3 = __float2half_rn(v.w);
        __half l0 = __float2half_rn(v.x - __half2float(h0));
        __half l1 = __float2half_rn(v.y - __half2float(h1));
        __half l2 = __float2half_rn(v.z - __half2float(h2));
        __half l3 = __float2half_rn(v.w - __half2float(h3));
        uint32_t off = jl * BSTRIDE + c4 * 2;
        *(uint2*)(smem + SM_B + off)          = make_uint2(pkh(h0, h1), pkh(h2, h3));
        *(uint2*)(smem + SM_B + B_HALF + off) = make_uint2(pkh(l0, l1), pkh(l2, l3));
    }
    __syncthreads();

    // ---- lane mappings ----
    const int a_row = wm * 64 + (lane & 15);
    const int a_kb  = ((lane >> 4) & 1) * 16;
    const int b_row = wn * 32 + (lane & 7) + ((lane >> 4) << 3);
    const int b_kb  = ((lane >> 3) & 1) * 16;
    const float* bias = jhalf ? g_zero : b1;

    // ---- tile loop ----
    for (int it = 0; it < 6; ++it) {
        const int rt = (bid >> 1) + it * 148;
        if (rt >= NTILES) break;
        const int row0 = rt * 128;

        // A chunk load (32 f32 cols) -> 4 float4 per thread
        auto ldgA = [&](int c, float4* rA) {
            #pragma unroll
            for (int r = 0; r < 4; ++r) {
                int idx4 = r * 256 + tid;
                int row = idx4 >> 3;
                int c4  = (idx4 & 7) << 2;
                int gr = row0 + row;
                rA[r] = make_float4(0.f, 0.f, 0.f, 0.f);
                if (gr < N_NODES)
                    rA[r] = *(const float4*)(feat + (size_t)gr * IN_FEAT + c * 32 + c4);
            }
        };
        auto stsA = [&](int st, const float4* rA) {
            #pragma unroll
            for (int r = 0; r < 4; ++r) {
                int idx4 = r * 256 + tid;
                int row = idx4 >> 3;
                int c4  = (idx4 & 7) << 2;
                float4 v = rA[r];
                uint2 hv = make_uint2(
                    pkh(__float2half_rn(v.x), __float2half_rn(v.y)),
                    pkh(__float2half_rn(v.z), __float2half_rn(v.w)));
                *(uint2*)(smem + SM_A + st * A_CH + row * CH2 + c4 * 2) = hv;
            }
        };

        float acc[4][4][4];
        #pragma unroll
        for (int i = 0; i < 4; ++i)
            #pragma unroll
            for (int j = 0; j < 4; ++j)
                #pragma unroll
                for (int q = 0; q < 4; ++q) acc[i][j][q] = 0.f;

        // mma over one A stage vs resident Whi then Wlo, K-chunk kc (32 wide)
        auto mma_st = [&](int st, int kc) {
            const uint32_t abase = sb + SM_A + st * A_CH;
            #pragma unroll
            for (int pass = 0; pass < 2; ++pass) {
                const uint32_t bbh = sb + SM_B + pass * B_HALF;
                #pragma unroll
                for (int ks = 0; ks < 2; ++ks) {
                    const int akb = ks * 32;
                    const int bkb = kc * 64 + ks * 32;
                    uint32_t afr[4][4];
                    #pragma unroll
                    for (int mt = 0; mt < 4; ++mt)
                        ldmx4(abase + (a_row + mt * 16) * CH2 + akb + a_kb,
                              afr[mt][0], afr[mt][1], afr[mt][2], afr[mt][3]);
                    uint32_t bfr[4][2];
                    #pragma unroll
                    for (int t = 0; t < 2; ++t) {
                        uint32_t r0, r1, r2, r3;
                        ldmx4(bbh + (b_row + 16 * t) * BSTRIDE + bkb + b_kb,
                              r0, r1, r2, r3);
                        bfr[2 * t][0] = r0; bfr[2 * t][1] = r1;
                        bfr[2 * t + 1][0] = r2; bfr[2 * t + 1][1] = r3;
                    }
                    #pragma unroll
                    for (int mt = 0; mt < 4; ++mt)
                        #pragma unroll
                        for (int nt = 0; nt < 4; ++nt)
                            mma_f16(acc[mt][nt], afr[mt], bfr[nt]);
                }
            }
        };

        // pipeline: 4 A chunks, 2 stages
        float4 rA[4];
        ldgA(0, rA);
        stsA(0, rA);
        ldgA(1, rA);

        __syncthreads();
        mma_st(0, 0);
        stsA(1, rA);
        ldgA(2, rA);

        __syncthreads();
        mma_st(1, 1);
        stsA(0, rA);
        ldgA(3, rA);

        __syncthreads();
        mma_st(0, 2);
        stsA(1, rA);

        __syncthreads();
        mma_st(1, 3);

        // epilogue: +bias, fp16 store
        #pragma unroll
        for (int mt = 0; mt < 4; ++mt) {
            const int r_lo = row0 + wm * 64 + mt * 16 + (lane >> 2);
            #pragma unroll
            for (int nt = 0; nt < 4; ++nt) {
                const int lcol = wn * 32 + nt * 8 + (lane & 3) * 2;
                const float2 bv = *(const float2*)(bias + lcol);
                const int gcol = jcol0 + lcol;
                if (r_lo < N_NODES)
                    *(__half2*)(g_node + (size_t)r_lo * NOUT + gcol) =
                        __floats2half2_rn(acc[mt][nt][0] + bv.x, acc[mt][nt][1] + bv.y);
                if (r_lo + 8 < N_NODES)
                    *(__half2*)(g_node + (size_t)(r_lo + 8) * NOUT + gcol) =
                        __floats2half2_rn(acc[mt][nt][2] + bv.x, acc[mt][nt][3] + bv.y);
            }
        }
        // Cross-iteration safety: next stsA(0) overwrites stage0, last read in
        // this tile's mma_st(0, 2), which completed before the final barrier.
    }
}

// ---------------------------------------------------------------------------
// Edge score, 16 edges/warp, 2 edges per round (16 lanes each).
// Bias pre-folded into g_node's A half: hid = relu_h2(A[src] + B[dst]);
// score = dot(hid, W2) + b2 (dot in fp32).
// ---------------------------------------------------------------------------
__device__ __forceinline__ __half2 h2(uint32_t u) {
    return *reinterpret_cast<const __half2*>(&u);
}

__global__ __launch_bounds__(256) void edge_score_kernel(
    const int* __restrict__ src,
    const int* __restrict__ dst,
    const float* __restrict__ W2,
    const float* __restrict__ b2,
    float* __restrict__ out,
    int E)
{
    const int warp = (blockIdx.x * blockDim.x + threadIdx.x) >> 5;
    const int lane = threadIdx.x & 31;
    const int base = warp * 16;
    if (base >= E) return;

    const int l15 = lane & 15;
    const float4 w0 = ((const float4*)W2)[l15 * 2];
    const float4 w1 = ((const float4*)W2)[l15 * 2 + 1];
    const float bb = b2[0];
    const __half2 z2 = __float2half2_rn(0.f);

    const int eidx = base + l15;
    int node = 0;
    if (eidx < E) node = (lane < 16) ? src[eidx] : dst[eidx];
    node = min(max(node, 0), N_NODES - 1);
    uint32_t off = (uint32_t)node * (NOUT * 2) + ((lane >= 16) ? (IN_FEAT * 2) : 0);

    const char* gbase = (const char*)g_node;
    const int g = lane >> 4;           // group: 0 -> even edge, 1 -> odd edge
    float res = 0.f;

    #pragma unroll
    for (int r = 0; r < 8; ++r) {
        const int e = 2 * r + g;
        const uint32_t so = __shfl_sync(0xffffffffu, off, e);
        const uint32_t dofs = __shfl_sync(0xffffffffu, off, 16 + e);
        const uint4 ua = *(const uint4*)(gbase + so + l15 * 16);
        const uint4 ub = *(const uint4*)(gbase + dofs + l15 * 16);

        const __half2 s0 = __hmax2(__hadd2(h2(ua.x), h2(ub.x)), z2);
        const __half2 s1 = __hmax2(__hadd2(h2(ua.y), h2(ub.y)), z2);
        const __half2 s2 = __hmax2(__hadd2(h2(ua.z), h2(ub.z)), z2);
        const __half2 s3 = __hmax2(__hadd2(h2(ua.w), h2(ub.w)), z2);

        const float2 f0 = __half22float2(s0);
        const float2 f1 = __half22float2(s1);
        const float2 f2 = __half22float2(s2);
        const float2 f3 = __half22float2(s3);

        float p = fmaf(f0.x, w0.x, fmaf(f0.y, w0.y, fmaf(f1.x, w0.z, f1.y * w0.w)));
        p = fmaf(f2.x, w1.x, fmaf(f2.y, w1.y, fmaf(f3.x, w1.z, fmaf(f3.y, w1.w, p))));

        #pragma unroll
        for (int o = 8; o; o >>= 1)
            p += __shfl_xor_sync(0xffffffffu, p, o);

        if (lane == 2 * r + 17 * g) res = p + bb;
    }

    const float other = __shfl_sync(0xffffffffu, res, (lane + 16) & 31);
    const float val = (lane & 1) ? other : res;
    if (lane < 16 && base + lane < E) out[base + lane] = val;
}

// ---------------------------------------------------------------------------
// Launch.  Inputs: 0 feature[100000,128] f32, 1 src[800000] i32,
// 2 dst[800000] i32, 3 W1[128,256] f32, 4 b1[128] f32, 5 W2[1,128] f32,
// 6 b2[1] f32.  Output: score[800000,1] f32.
// ---------------------------------------------------------------------------
extern "C" void kernel_launch(void* const* d_in, const int* in_sizes, int n_in,
                              void* d_out, int out_size) {
    const float* feat = (const float*)d_in[0];
    const int*   src  = (const int*)d_in[1];
    const int*   dst  = (const int*)d_in[2];
    const float* W1   = (const float*)d_in[3];
    const float* b1   = (const float*)d_in[4];
    const float* W2   = (const float*)d_in[5];
    const float* b2   = (const float*)d_in[6];
    float*       out  = (float*)d_out;

    const int E = in_sizes[1];

    cudaFuncSetAttribute(node_gemm_mma, cudaFuncAttributeMaxDynamicSharedMemorySize, SMEM_TOTAL);
    node_gemm_mma<<<296, 256, SMEM_TOTAL>>>(feat, W1, b1);

    const int nblocks = (E + 127) / 128;   // 8 warps x 16 edges per block
    edge_score_kernel<<<nblocks, 256>>>(src, dst, W2, b2, out, E);
}

// round 16
// speedup vs baseline: 4.1316x; 1.2314x over previous
#include <cuda_runtime.h>
#include <cuda_bf16.h>
#include <cuda_fp16.h>
#include <cstdint>

#define N_NODES 100000
#define IN_FEAT 128
#define NOUT 256           // fused outputs per node: [A(128) | B(128)]
#define NTILES 782         // ceil(100000/128)

// Per-node A|B rows in fp16 (51.2 MB, L2-resident).
__device__ __half g_node[(size_t)N_NODES * NOUT];
__device__ float g_zero[IN_FEAT];   // zero bias for the B half

__device__ __forceinline__ uint32_t s2u(const void* p) {
    uint32_t a;
    asm("{ .reg .u64 t; cvta.to.shared.u64 t, %1; cvt.u32.u64 %0, t; }" : "=r"(a) : "l"(p));
    return a;
}
__device__ __forceinline__ uint32_t pkh(__half a, __half b) {
    __half2 t(a, b);
    return *reinterpret_cast<uint32_t*>(&t);
}

// ---------------------------------------------------------------------------
// Persistent node GEMM via mma.sync fp16 (HMMA), single pass:
//   out = a_f16 * w_f16   (fp32 accumulate, +bias, fp16 store)
// fp16 rounding of A and W each contribute ~2.5-3e-4 RMS; combined with the
// fp16 g_node storage this stays ~5e-4, 2x under the 1e-3 gate.
// 296 CTAs (2/SM). jhalf = bid&1 selects W1[:, :128] (src, bias b1) or
// W1[:, 128:] (dst, bias 0). W block converted once into resident smem
// (stride 272, conflict-free ldmatrix). Row-tiles rt = (bid>>1) + 148*it
// stream A as four 32-col chunks through a 2-stage fp16 buffer (stride 80).
// 8 warps (2M x 4N), warp tile 64x32.
// ---------------------------------------------------------------------------
#define CH2 80
#define A_CH 10240                  // 128 rows * 80B (fp16)
#define SM_A 0                      // A[stage] at st*A_CH
#define BSTRIDE 272
#define B_BYTES (128 * BSTRIDE)     // 34816
#define SM_B (2 * A_CH)             // 20480
#define SMEM_TOTAL (SM_B + B_BYTES) // 55296

__device__ __forceinline__ void ldmx4(uint32_t addr, uint32_t& r0, uint32_t& r1,
                                      uint32_t& r2, uint32_t& r3) {
    asm volatile("ldmatrix.sync.aligned.m8n8.x4.shared.b16 {%0,%1,%2,%3}, [%4];"
                 : "=r"(r0), "=r"(r1), "=r"(r2), "=r"(r3) : "r"(addr));
}
__device__ __forceinline__ void mma_f16(float* d, const uint32_t* a, const uint32_t* b) {
    asm volatile(
        "mma.sync.aligned.m16n8k16.row.col.f32.f16.f16.f32 "
        "{%0,%1,%2,%3}, {%4,%5,%6,%7}, {%8,%9}, {%0,%1,%2,%3};"
        : "+f"(d[0]), "+f"(d[1]), "+f"(d[2]), "+f"(d[3])
        : "r"(a[0]), "r"(a[1]), "r"(a[2]), "r"(a[3]), "r"(b[0]), "r"(b[1]));
}

__global__ __launch_bounds__(256, 2) void node_gemm_mma(
    const float* __restrict__ feat, const float* __restrict__ W1,
    const float* __restrict__ b1)
{
    extern __shared__ __align__(16) char smem[];
    const uint32_t sb = s2u(smem);
    const int tid  = threadIdx.x;
    const int lane = tid & 31;
    const int wid  = tid >> 5;
    const int wm   = wid & 1;            // 64-row warp band
    const int wn   = wid >> 1;           // 32-col warp band (0..3)
    const int bid  = blockIdx.x;
    const int jhalf = bid & 1;
    const int jcol0 = jhalf * 128;

    // ---- init: fp16-convert this CTA's W1 block into resident smem ----
    // w(jl, k) = W1[jl][jhalf*128 + k]
    #pragma unroll
    for (int r = 0; r < 16; ++r) {
        int idx4 = r * 256 + tid;            // 4096 float4 (128 j x 32 f4)
        int jl = idx4 >> 5;
        int c4 = (idx4 & 31) << 2;
        float4 v = *(const float4*)(W1 + (size_t)jl * NOUT + jhalf * 128 + c4);
        uint2 hv = make_uint2(
            pkh(__float2half_rn(v.x), __float2half_rn(v.y)),
            pkh(__float2half_rn(v.z), __float2half_rn(v.w)));
        *(uint2*)(smem + SM_B + jl * BSTRIDE + c4 * 2) = hv;
    }
    __syncthreads();

    // ---- lane mappings ----
    const int a_row = wm * 64 + (lane & 15);
    const int a_kb  = ((lane >> 4) & 1) * 16;
    const int b_row = wn * 32 + (lane & 7) + ((lane >> 4) << 3);
    const int b_kb  = ((lane >> 3) & 1) * 16;
    const float* bias = jhalf ? g_zero : b1;

    // ---- tile loop ----
    for (int it = 0; it < 6; ++it) {
        const int rt = (bid >> 1) + it * 148;
        if (rt >= NTILES) break;
        const int row0 = rt * 128;

        // A chunk load (32 f32 cols) -> 4 float4 per thread
        auto ldgA = [&](int c, float4* rA) {
            #pragma unroll
            for (int r = 0; r < 4; ++r) {
                int idx4 = r * 256 + tid;
                int row = idx4 >> 3;
                int c4  = (idx4 & 7) << 2;
                int gr = row0 + row;
                rA[r] = make_float4(0.f, 0.f, 0.f, 0.f);
                if (gr < N_NODES)
                    rA[r] = *(const float4*)(feat + (size_t)gr * IN_FEAT + c * 32 + c4);
            }
        };
        auto stsA = [&](int st, const float4* rA) {
            #pragma unroll
            for (int r = 0; r < 4; ++r) {
                int idx4 = r * 256 + tid;
                int row = idx4 >> 3;
                int c4  = (idx4 & 7) << 2;
                float4 v = rA[r];
                uint2 hv = make_uint2(
                    pkh(__float2half_rn(v.x), __float2half_rn(v.y)),
                    pkh(__float2half_rn(v.z), __float2half_rn(v.w)));
                *(uint2*)(smem + SM_A + st * A_CH + row * CH2 + c4 * 2) = hv;
            }
        };

        float acc[4][4][4];
        #pragma unroll
        for (int i = 0; i < 4; ++i)
            #pragma unroll
            for (int j = 0; j < 4; ++j)
                #pragma unroll
                for (int q = 0; q < 4; ++q) acc[i][j][q] = 0.f;

        // mma over one A stage vs resident W, K-chunk kc (32 wide)
        auto mma_st = [&](int st, int kc) {
            const uint32_t abase = sb + SM_A + st * A_CH;
            const uint32_t bbh = sb + SM_B;
            #pragma unroll
            for (int ks = 0; ks < 2; ++ks) {
                const int akb = ks * 32;
                const int bkb = kc * 64 + ks * 32;
                uint32_t afr[4][4];
                #pragma unroll
                for (int mt = 0; mt < 4; ++mt)
                    ldmx4(abase + (a_row + mt * 16) * CH2 + akb + a_kb,
                          afr[mt][0], afr[mt][1], afr[mt][2], afr[mt][3]);
                uint32_t bfr[4][2];
                #pragma unroll
                for (int t = 0; t < 2; ++t) {
                    uint32_t r0, r1, r2, r3;
                    ldmx4(bbh + (b_row + 16 * t) * BSTRIDE + bkb + b_kb,
                          r0, r1, r2, r3);
                    bfr[2 * t][0] = r0; bfr[2 * t][1] = r1;
                    bfr[2 * t + 1][0] = r2; bfr[2 * t + 1][1] = r3;
                }
                #pragma unroll
                for (int mt = 0; mt < 4; ++mt)
                    #pragma unroll
                    for (int nt = 0; nt < 4; ++nt)
                        mma_f16(acc[mt][nt], afr[mt], bfr[nt]);
            }
        };

        // pipeline: 4 A chunks, 2 stages
        float4 rA[4];
        ldgA(0, rA);
        stsA(0, rA);
        ldgA(1, rA);

        __syncthreads();
        mma_st(0, 0);
        stsA(1, rA);
        ldgA(2, rA);

        __syncthreads();
        mma_st(1, 1);
        stsA(0, rA);
        ldgA(3, rA);

        __syncthreads();
        mma_st(0, 2);
        stsA(1, rA);

        __syncthreads();
        mma_st(1, 3);

        // epilogue: +bias, fp16 store
        #pragma unroll
        for (int mt = 0; mt < 4; ++mt) {
            const int r_lo = row0 + wm * 64 + mt * 16 + (lane >> 2);
            #pragma unroll
            for (int nt = 0; nt < 4; ++nt) {
                const int lcol = wn * 32 + nt * 8 + (lane & 3) * 2;
                const float2 bv = *(const float2*)(bias + lcol);
                const int gcol = jcol0 + lcol;
                if (r_lo < N_NODES)
                    *(__half2*)(g_node + (size_t)r_lo * NOUT + gcol) =
                        __floats2half2_rn(acc[mt][nt][0] + bv.x, acc[mt][nt][1] + bv.y);
                if (r_lo + 8 < N_NODES)
                    *(__half2*)(g_node + (size_t)(r_lo + 8) * NOUT + gcol) =
                        __floats2half2_rn(acc[mt][nt][2] + bv.x, acc[mt][nt][3] + bv.y);
            }
        }
        // Cross-iteration safety: next stsA(0) overwrites stage0, last read in
        // this tile's mma_st(0, 2), which completed before the final barrier.
    }
}

// ---------------------------------------------------------------------------
// Edge score, 16 edges/warp, 2 edges per round (16 lanes each).
// Bias pre-folded into g_node's A half: hid = relu_h2(A[src] + B[dst]);
// score = dot(hid, W2) + b2 (dot in fp32).
// ---------------------------------------------------------------------------
__device__ __forceinline__ __half2 h2(uint32_t u) {
    return *reinterpret_cast<const __half2*>(&u);
}

__global__ __launch_bounds__(256) void edge_score_kernel(
    const int* __restrict__ src,
    const int* __restrict__ dst,
    const float* __restrict__ W2,
    const float* __restrict__ b2,
    float* __restrict__ out,
    int E)
{
    const int warp = (blockIdx.x * blockDim.x + threadIdx.x) >> 5;
    const int lane = threadIdx.x & 31;
    const int base = warp * 16;
    if (base >= E) return;

    const int l15 = lane & 15;
    const float4 w0 = ((const float4*)W2)[l15 * 2];
    const float4 w1 = ((const float4*)W2)[l15 * 2 + 1];
    const float bb = b2[0];
    const __half2 z2 = __float2half2_rn(0.f);

    const int eidx = base + l15;
    int node = 0;
    if (eidx < E) node = (lane < 16) ? src[eidx] : dst[eidx];
    node = min(max(node, 0), N_NODES - 1);
    uint32_t off = (uint32_t)node * (NOUT * 2) + ((lane >= 16) ? (IN_FEAT * 2) : 0);

    const char* gbase = (const char*)g_node;
    const int g = lane >> 4;           // group: 0 -> even edge, 1 -> odd edge
    float res = 0.f;

    #pragma unroll
    for (int r = 0; r < 8; ++r) {
        const int e = 2 * r + g;
        const uint32_t so = __shfl_sync(0xffffffffu, off, e);
        const uint32_t dofs = __shfl_sync(0xffffffffu, off, 16 + e);
        const uint4 ua = *(const uint4*)(gbase + so + l15 * 16);
        const uint4 ub = *(const uint4*)(gbase + dofs + l15 * 16);

        const __half2 s0 = __hmax2(__hadd2(h2(ua.x), h2(ub.x)), z2);
        const __half2 s1 = __hmax2(__hadd2(h2(ua.y), h2(ub.y)), z2);
        const __half2 s2 = __hmax2(__hadd2(h2(ua.z), h2(ub.z)), z2);
        const __half2 s3 = __hmax2(__hadd2(h2(ua.w), h2(ub.w)), z2);

        const float2 f0 = __half22float2(s0);
        const float2 f1 = __half22float2(s1);
        const float2 f2 = __half22float2(s2);
        const float2 f3 = __half22float2(s3);

        float p = fmaf(f0.x, w0.x, fmaf(f0.y, w0.y, fmaf(f1.x, w0.z, f1.y * w0.w)));
        p = fmaf(f2.x, w1.x, fmaf(f2.y, w1.y, fmaf(f3.x, w1.z, fmaf(f3.y, w1.w, p))));

        #pragma unroll
        for (int o = 8; o; o >>= 1)
            p += __shfl_xor_sync(0xffffffffu, p, o);

        if (lane == 2 * r + 17 * g) res = p + bb;
    }

    const float other = __shfl_sync(0xffffffffu, res, (lane + 16) & 31);
    const float val = (lane & 1) ? other : res;
    if (lane < 16 && base + lane < E) out[base + lane] = val;
}

// ---------------------------------------------------------------------------
// Launch.  Inputs: 0 feature[100000,128] f32, 1 src[800000] i32,
// 2 dst[800000] i32, 3 W1[128,256] f32, 4 b1[128] f32, 5 W2[1,128] f32,
// 6 b2[1] f32.  Output: score[800000,1] f32.
// ---------------------------------------------------------------------------
extern "C" void kernel_launch(void* const* d_in, const int* in_sizes, int n_in,
                              void* d_out, int out_size) {
    const float* feat = (const float*)d_in[0];
    const int*   src  = (const int*)d_in[1];
    const int*   dst  = (const int*)d_in[2];
    const float* W1   = (const float*)d_in[3];
    const float* b1   = (const float*)d_in[4];
    const float* W2   = (const float*)d_in[5];
    const float* b2   = (const float*)d_in[6];
    float*       out  = (float*)d_out;

    const int E = in_sizes[1];

    cudaFuncSetAttribute(node_gemm_mma, cudaFuncAttributeMaxDynamicSharedMemorySize, SMEM_TOTAL);
    node_gemm_mma<<<296, 256, SMEM_TOTAL>>>(feat, W1, b1);

    const int nblocks = (E + 127) / 128;   // 8 warps x 16 edges per block
    edge_score_kernel<<<nblocks, 256>>>(src, dst, W2, b2, out, E);
}